// round 9
// baseline (speedup 1.0000x reference)
#include <cuda_runtime.h>
#include <mma.h>
#include <cstdint>
#include <cstddef>

using namespace nvcuda;

#define N_NODES 8192
#define IN_C    512
#define HID_C   1024
#define OUT_C   256

// ---------------- scratch (static device arrays; no allocations) ----------------
__device__ float g_inv [N_NODES];
__device__ float g_asum[N_NODES];                      // rowsum of normalized Â
__device__ float g_edge[(size_t)N_NODES * N_NODES];    // normalized adjacency, tf32-rounded
__device__ float g_XT  [(size_t)IN_C * N_NODES];       // X^T, tf32-rounded [512, 8192]
__device__ float g_W1r [(size_t)HID_C * IN_C];
__device__ float g_W2r [(size_t)OUT_C * HID_C];
__device__ float g_G   [(size_t)N_NODES * IN_C];       // Â@X [8192,512]; later D0/D1 splits
__device__ float g_C   [(size_t)N_NODES * HID_C];      // GEMM out buffer; later C0/C1 splits
__device__ float g_H   [(size_t)N_NODES * HID_C];      // relu hidden, tf32-rounded
__device__ float g_OsT [(size_t)OUT_C * N_NODES];      // (H@W2^T)^T, tf32-rounded

__device__ __forceinline__ float f2tf32(float x) {
    float r; asm("cvt.rna.tf32.f32 %0, %1;" : "=f"(r) : "f"(x)); return r;
}
__device__ __forceinline__ uint32_t smem_u32(const void* p) {
    uint32_t a;
    asm("{ .reg .u64 t; cvta.to.shared.u64 t, %1; cvt.u32.u64 %0, t; }" : "=r"(a) : "l"(p));
    return a;
}
__device__ __forceinline__ void cp16(uint32_t dst, const void* src) {
    asm volatile("cp.async.cg.shared.global [%0], [%1], 16;" :: "r"(dst), "l"(src));
}
#define CP_COMMIT() asm volatile("cp.async.commit_group;" ::: "memory")
#define CP_WAIT2()  asm volatile("cp.async.wait_group 2;" ::: "memory")

// ---- wmma tf32 GEMM: 256x128 block, 512 thr, 16 warps of 64x32, 4-stage cp.async ----
// C[M, Ncols] = A[M, Klen] @ B[Ncols, Klen]^T (both K-major, pre-rounded tf32).
// blockIdx.z = split-K slice: koff = z*Klen, C += z*csplit.
constexpr int NTHR = 512;
constexpr int BM = 256, BN = 128, BK = 32;
constexpr int BKP = 36;                                   // 144 B/row; 12r mod 32 distinct
constexpr int STAGES = 4;
constexpr int A_STAGE_B = BM * BKP * 4;                   // 36864
constexpr int STAGE_B   = (BM + BN) * BKP * 4;            // 55296
constexpr int SMEM_GEMM = STAGES * STAGE_B;               // 221184
constexpr int WMI = 4, WNI = 2;                           // 64x32 warp tile, 4x4 warp grid

__global__ __launch_bounds__(NTHR, 1) void tc_gemm(
    const float* __restrict__ A, const float* __restrict__ B,
    float* __restrict__ C, int strideA, int strideB,
    int Klen, int Ncols, size_t csplit)
{
    extern __shared__ __align__(16) char smem[];
    float* sf = reinterpret_cast<float*>(smem);
    const uint32_t sb = smem_u32(smem);

    const int tid  = threadIdx.x;
    const int warp = tid >> 5;
    const int bm0  = blockIdx.y * BM;
    const int bn0  = blockIdx.x * BN;
    const int koff = blockIdx.z * Klen;
    C += (size_t)blockIdx.z * csplit;
    const int wm0 = (warp >> 2) * 64;    // 4 warp rows
    const int wn0 = (warp & 3) * 32;     // 4 warp cols
    const int NKB = Klen / BK;

    wmma::fragment<wmma::accumulator, 16, 16, 8, float> acc[WMI][WNI];
    #pragma unroll
    for (int i = 0; i < WMI; i++)
        #pragma unroll
        for (int j = 0; j < WNI; j++)
            wmma::fill_fragment(acc[i][j], 0.f);

    const float* Abase = A + (size_t)bm0 * strideA + koff;
    const float* Bbase = B + (size_t)bn0 * strideB + koff;

    const int lr = tid >> 3;             // 0..63 (64 rows per pass)
    const int lc = tid & 7;              // 16B chunk within 128B of K data

    auto load_stage = [&](int s, int kb) {
        const uint32_t abase = sb + s * STAGE_B;
        const uint32_t bbase = abase + A_STAGE_B;
        const float* Ag = Abase + (size_t)kb * BK;
        const float* Bg = Bbase + (size_t)kb * BK;
        #pragma unroll
        for (int i = 0; i < 4; i++) {    // A: 256 rows
            const int row = lr + i * 64;
            cp16(abase + row * (BKP * 4) + lc * 16, Ag + (size_t)row * strideA + lc * 4);
        }
        #pragma unroll
        for (int i = 0; i < 2; i++) {    // B: 128 rows
            const int row = lr + i * 64;
            cp16(bbase + row * (BKP * 4) + lc * 16, Bg + (size_t)row * strideB + lc * 4);
        }
    };

    #pragma unroll
    for (int p = 0; p < STAGES - 1; p++) { load_stage(p, p); CP_COMMIT(); }

    for (int kb = 0; kb < NKB; kb++) {
        CP_WAIT2();                  // stage kb resident
        __syncthreads();             // all warps done reading stage (kb-1)%STAGES
        const int j = kb + (STAGES - 1);
        if (j < NKB) load_stage(j % STAGES, j);
        CP_COMMIT();                 // uniform group numbering (empty at tail)

        const int s = kb % STAGES;
        float* As = sf + (size_t)s * (STAGE_B / 4);
        float* Bs = As + (A_STAGE_B / 4);

        #pragma unroll
        for (int ks = 0; ks < BK / 8; ++ks) {
            wmma::fragment<wmma::matrix_a, 16, 16, 8, wmma::precision::tf32, wmma::row_major> af[WMI];
            wmma::fragment<wmma::matrix_b, 16, 16, 8, wmma::precision::tf32, wmma::col_major> bf[WNI];
            #pragma unroll
            for (int i = 0; i < WMI; i++)
                wmma::load_matrix_sync(af[i], As + (size_t)(wm0 + i * 16) * BKP + ks * 8, BKP);
            #pragma unroll
            for (int jf = 0; jf < WNI; jf++)
                wmma::load_matrix_sync(bf[jf], Bs + (size_t)(wn0 + jf * 16) * BKP + ks * 8, BKP);
            #pragma unroll
            for (int i = 0; i < WMI; i++)
                #pragma unroll
                for (int jf = 0; jf < WNI; jf++)
                    wmma::mma_sync(acc[i][jf], af[i], bf[jf], acc[i][jf]);
        }
    }

    #pragma unroll
    for (int i = 0; i < WMI; i++)
        #pragma unroll
        for (int j = 0; j < WNI; j++)
            wmma::store_matrix_sync(
                &C[(size_t)(bm0 + wm0 + i * 16) * Ncols + (bn0 + wn0 + j * 16)],
                acc[i][j], Ncols, wmma::mem_row_major);
}

// ---------------- pre/post kernels ----------------
__global__ void rowsum_rsqrt(const float* __restrict__ mat, float* __restrict__ out) {
    const int row = blockIdx.x;
    const float4* p = reinterpret_cast<const float4*>(mat + (size_t)row * N_NODES);
    float s = 0.f;
    for (int j = threadIdx.x; j < N_NODES / 4; j += blockDim.x) {
        float4 v = p[j]; s += (v.x + v.y) + (v.z + v.w);
    }
    #pragma unroll
    for (int o = 16; o > 0; o >>= 1) s += __shfl_down_sync(0xffffffffu, s, o);
    __shared__ float red[8];
    const int lane = threadIdx.x & 31, w = threadIdx.x >> 5;
    if (lane == 0) red[w] = s;
    __syncthreads();
    if (w == 0) {
        s = (lane < 8) ? red[lane] : 0.f;
        #pragma unroll
        for (int o = 4; o > 0; o >>= 1) s += __shfl_down_sync(0xffffffffu, s, o);
        if (lane == 0) out[row] = (s > 0.f) ? rsqrtf(s) : 0.f;
    }
}

// Asc[i,j] = rna(inv[i]*edge[i,j]*inv[j]); asum[i] = rowsum(Asc[i,:]) (fused)
__global__ void norm_edge_rowsum(const float* __restrict__ edge, const float* __restrict__ inv,
                                 float* __restrict__ out, float* __restrict__ asum) {
    const int row = blockIdx.x;
    const float s = inv[row];
    const float4* p  = reinterpret_cast<const float4*>(edge + (size_t)row * N_NODES);
    const float4* iv = reinterpret_cast<const float4*>(inv);
    float4* q = reinterpret_cast<float4*>(out + (size_t)row * N_NODES);
    float acc = 0.f;
    for (int j = threadIdx.x; j < N_NODES / 4; j += blockDim.x) {
        float4 v = p[j];
        float4 w = iv[j];
        float4 o = make_float4(f2tf32(s * v.x * w.x), f2tf32(s * v.y * w.y),
                               f2tf32(s * v.z * w.z), f2tf32(s * v.w * w.w));
        q[j] = o;
        acc += (o.x + o.y) + (o.z + o.w);
    }
    #pragma unroll
    for (int o = 16; o > 0; o >>= 1) acc += __shfl_down_sync(0xffffffffu, acc, o);
    __shared__ float red[8];
    const int lane = threadIdx.x & 31, w = threadIdx.x >> 5;
    if (lane == 0) red[w] = acc;
    __syncthreads();
    if (w == 0) {
        acc = (lane < 8) ? red[lane] : 0.f;
        #pragma unroll
        for (int o = 4; o > 0; o >>= 1) acc += __shfl_down_sync(0xffffffffu, acc, o);
        if (lane == 0) asum[row] = acc;
    }
}

__global__ void conv_rna(const float* __restrict__ in, float* __restrict__ out) {
    const size_t i = ((size_t)blockIdx.x * blockDim.x + threadIdx.x) * 4;
    float4 v = *reinterpret_cast<const float4*>(in + i);
    float4 o = make_float4(f2tf32(v.x), f2tf32(v.y), f2tf32(v.z), f2tf32(v.w));
    *reinterpret_cast<float4*>(out + i) = o;
}

__global__ void epi_rna(const float* __restrict__ in, float* __restrict__ out) {
    const size_t i = ((size_t)blockIdx.x * blockDim.x + threadIdx.x) * 4;
    float4 v = *reinterpret_cast<const float4*>(in + i);
    float4 o = make_float4(f2tf32(v.x), f2tf32(v.y), f2tf32(v.z), f2tf32(v.w));
    *reinterpret_cast<float4*>(out + i) = o;
}

// XT[c, n] = rna(X[n, c]); X is [N_NODES, IN_C]
__global__ void transpose_x_rna(const float* __restrict__ X, float* __restrict__ XT) {
    __shared__ float t[32][33];
    const int bx = blockIdx.x * 32, by = blockIdx.y * 32;
    const int x = threadIdx.x, y = threadIdx.y;   // 32 x 8
    #pragma unroll
    for (int yy = y; yy < 32; yy += 8)
        t[yy][x] = X[(size_t)(by + yy) * IN_C + bx + x];
    __syncthreads();
    #pragma unroll
    for (int yy = y; yy < 32; yy += 8)
        XT[(size_t)(bx + yy) * N_NODES + by + x] = f2tf32(t[x][yy]);
}

// outT[n, m] = rna(D0[m,n] + D1[m,n]); D is [M, Ncols]
__global__ void epi_transpose_sum2_rna(const float* __restrict__ D0, const float* __restrict__ D1,
                                       float* __restrict__ outT, int M, int Ncols) {
    __shared__ float t[32][33];
    const int bx = blockIdx.x * 32, by = blockIdx.y * 32;
    const int x = threadIdx.x, y = threadIdx.y;   // 32 x 8
    #pragma unroll
    for (int yy = y; yy < 32; yy += 8) {
        const size_t idx = (size_t)(by + yy) * Ncols + bx + x;
        t[yy][x] = D0[idx] + D1[idx];
    }
    __syncthreads();
    #pragma unroll
    for (int yy = y; yy < 32; yy += 8)
        outT[(size_t)(bx + yy) * M + by + x] = f2tf32(t[x][yy]);
}

// H[m,j] = rna(relu(C[m,j] + asum[m]*b1[j]))
__global__ void epi_relu_biasrow_rna(const float* __restrict__ C, const float* __restrict__ asum,
                                     const float* __restrict__ bias, float* __restrict__ out,
                                     int Ncols) {
    const size_t i = (size_t)blockIdx.x * blockDim.x + threadIdx.x;    // float4 idx
    const int m  = (int)(i / (Ncols / 4));
    const int j4 = (int)(i % (Ncols / 4)) * 4;
    const float a = __ldg(asum + m);
    float4 c = *reinterpret_cast<const float4*>(C + (size_t)m * Ncols + j4);
    float4 b = *reinterpret_cast<const float4*>(bias + j4);
    float4 o = make_float4(f2tf32(fmaxf(c.x + a * b.x, 0.f)),
                           f2tf32(fmaxf(c.y + a * b.y, 0.f)),
                           f2tf32(fmaxf(c.z + a * b.z, 0.f)),
                           f2tf32(fmaxf(c.w + a * b.w, 0.f)));
    *reinterpret_cast<float4*>(out + (size_t)m * Ncols + j4) = o;
}

// out[m,j] = relu(C0[m,j] + C1[m,j] + asum[m]*b2[j])  (final, no rounding)
__global__ void epi_relu_biasrow_sum2(const float* __restrict__ C0, const float* __restrict__ C1,
                                      const float* __restrict__ asum, const float* __restrict__ bias,
                                      float* __restrict__ out, int Ncols) {
    const size_t i = (size_t)blockIdx.x * blockDim.x + threadIdx.x;
    const int m  = (int)(i / (Ncols / 4));
    const int j4 = (int)(i % (Ncols / 4)) * 4;
    const float a = __ldg(asum + m);
    const size_t off = (size_t)m * Ncols + j4;
    float4 c0 = *reinterpret_cast<const float4*>(C0 + off);
    float4 c1 = *reinterpret_cast<const float4*>(C1 + off);
    float4 b  = *reinterpret_cast<const float4*>(bias + j4);
    float4 o = make_float4(fmaxf(c0.x + c1.x + a * b.x, 0.f),
                           fmaxf(c0.y + c1.y + a * b.y, 0.f),
                           fmaxf(c0.z + c1.z + a * b.z, 0.f),
                           fmaxf(c0.w + c1.w + a * b.w, 0.f));
    *reinterpret_cast<float4*>(out + off) = o;
}

// ---------------- launch ----------------
extern "C" void kernel_launch(void* const* d_in, const int* in_sizes, int n_in,
                              void* d_out, int out_size) {
    const float* point = (const float*)d_in[0];
    const float* edge  = (const float*)d_in[1];
    const float* W1    = (const float*)d_in[2];
    const float* b1    = (const float*)d_in[3];
    const float* W2    = (const float*)d_in[4];
    const float* b2    = (const float*)d_in[5];
    float* out = (float*)d_out;

    float *inv, *asum, *Asc, *XT, *W1r, *W2r, *G, *C, *H, *OsT;
    cudaGetSymbolAddress((void**)&inv,  g_inv);
    cudaGetSymbolAddress((void**)&asum, g_asum);
    cudaGetSymbolAddress((void**)&Asc,  g_edge);
    cudaGetSymbolAddress((void**)&XT,   g_XT);
    cudaGetSymbolAddress((void**)&W1r,  g_W1r);
    cudaGetSymbolAddress((void**)&W2r,  g_W2r);
    cudaGetSymbolAddress((void**)&G,    g_G);
    cudaGetSymbolAddress((void**)&C,    g_C);
    cudaGetSymbolAddress((void**)&H,    g_H);
    cudaGetSymbolAddress((void**)&OsT,  g_OsT);

    cudaFuncSetAttribute(tc_gemm, cudaFuncAttributeMaxDynamicSharedMemorySize, SMEM_GEMM);

    const size_t SPLIT = (size_t)N_NODES * OUT_C;   // split-K partial buffer stride

    // #1..#3: normalization + X transpose (tc_gemm_a stays launch #4 for ncu)
    rowsum_rsqrt<<<N_NODES, 256>>>(edge, inv);
    norm_edge_rowsum<<<N_NODES, 256>>>(edge, inv, Asc, asum);
    transpose_x_rna<<<dim3(IN_C / 32, N_NODES / 32), dim3(32, 8)>>>(point, XT);

    // #4 GEMM_a: G = Asc @ X  [8192, 512]  (68.7 GF; 128 CTAs, 1 wave)
    tc_gemm<<<dim3(IN_C / BN, N_NODES / BM, 1), NTHR, SMEM_GEMM>>>(
        Asc, XT, G, N_NODES, N_NODES, N_NODES, IN_C, 0);

    // weight rounding (independent of GEMM_a; placed after to keep launch order)
    conv_rna<<<(HID_C * IN_C / 4) / 256, 256>>>(W1, W1r);
    conv_rna<<<(OUT_C * HID_C / 4) / 256, 256>>>(W2, W2r);
    epi_rna<<<(N_NODES * IN_C / 4) / 256, 256>>>(G, G);

    // GEMM_b: C = G @ W1^T  [8192, 1024]  (256 CTAs)
    tc_gemm<<<dim3(HID_C / BN, N_NODES / BM, 1), NTHR, SMEM_GEMM>>>(
        G, W1r, C, IN_C, IN_C, IN_C, HID_C, 0);
    epi_relu_biasrow_rna<<<(N_NODES * HID_C / 4) / 256, 256>>>(C, asum, b1, H, HID_C);

    // GEMM_c: split-K=2 -> D0,D1 in g_G  [8192, 256] each  (128 CTAs)
    tc_gemm<<<dim3(OUT_C / BN, N_NODES / BM, 2), NTHR, SMEM_GEMM>>>(
        H, W2r, G, HID_C, HID_C, HID_C / 2, OUT_C, SPLIT);
    epi_transpose_sum2_rna<<<dim3(OUT_C / 32, N_NODES / 32), dim3(32, 8)>>>(
        G, G + SPLIT, OsT, N_NODES, OUT_C);

    // GEMM_d: split-K=2 -> C0,C1 in g_C  [8192, 256] each  (128 CTAs)
    tc_gemm<<<dim3(OUT_C / BN, N_NODES / BM, 2), NTHR, SMEM_GEMM>>>(
        Asc, OsT, C, N_NODES, N_NODES, N_NODES / 2, OUT_C, SPLIT);
    epi_relu_biasrow_sum2<<<(N_NODES * OUT_C / 4) / 256, 256>>>(C, C + SPLIT, asum, b2, out, OUT_C);
}

// round 10
// speedup vs baseline: 1.0889x; 1.0889x over previous
#include <cuda_runtime.h>
#include <mma.h>
#include <cstdint>
#include <cstddef>

using namespace nvcuda;

#define N_NODES 8192
#define IN_C    512
#define HID_C   1024
#define OUT_C   256

// ---------------- scratch (static device arrays; no allocations) ----------------
__device__ float g_inv [N_NODES];
__device__ float g_asum[N_NODES];                      // rowsum of normalized Â
__device__ float g_edge[(size_t)N_NODES * N_NODES];    // normalized adjacency, tf32-rounded
__device__ float g_XT  [(size_t)IN_C * N_NODES];       // X^T, tf32-rounded [512, 8192]
__device__ float g_W1r [(size_t)HID_C * IN_C];
__device__ float g_W2r [(size_t)OUT_C * HID_C];
__device__ float g_G   [(size_t)N_NODES * IN_C];       // Â@X [8192,512]; later D0/D1 splits
__device__ float g_C   [(size_t)N_NODES * HID_C];      // GEMM out buffer; later C0/C1 splits
__device__ float g_H   [(size_t)N_NODES * HID_C];      // relu hidden, tf32-rounded
__device__ float g_OsT [(size_t)OUT_C * N_NODES];      // (H@W2^T)^T, tf32-rounded

__device__ __forceinline__ float f2tf32(float x) {
    float r; asm("cvt.rna.tf32.f32 %0, %1;" : "=f"(r) : "f"(x)); return r;
}
__device__ __forceinline__ uint32_t smem_u32(const void* p) {
    uint32_t a;
    asm("{ .reg .u64 t; cvta.to.shared.u64 t, %1; cvt.u32.u64 %0, t; }" : "=r"(a) : "l"(p));
    return a;
}
__device__ __forceinline__ void cp16(uint32_t dst, const void* src) {
    asm volatile("cp.async.cg.shared.global [%0], [%1], 16;" :: "r"(dst), "l"(src));
}
#define CP_COMMIT() asm volatile("cp.async.commit_group;" ::: "memory")
#define CP_WAIT2()  asm volatile("cp.async.wait_group 2;" ::: "memory")

// ---- wmma tf32 GEMM: 256x128 block, 256 thr, 8 warps of 64x64 (4x2 grid),
// ---- 4-stage cp.async, ks-level fragment double-buffering -------------------
// C[M, Ncols] = A[M, Klen] @ B[Ncols, Klen]^T (both K-major, pre-rounded tf32).
// blockIdx.z = split-K slice: koff = z*Klen, C += z*csplit.
constexpr int NTHR = 256;
constexpr int BM = 256, BN = 128, BK = 32;
constexpr int BKP = 36;                                   // 144 B/row; 12r mod 32 distinct
constexpr int STAGES = 4;
constexpr int A_STAGE_B = BM * BKP * 4;                   // 36864
constexpr int STAGE_B   = (BM + BN) * BKP * 4;            // 55296
constexpr int SMEM_GEMM = STAGES * STAGE_B;               // 221184
constexpr int WMI = 4, WNI = 4;                           // 64x64 warp tile

typedef wmma::fragment<wmma::matrix_a, 16, 16, 8, wmma::precision::tf32, wmma::row_major> FragA;
typedef wmma::fragment<wmma::matrix_b, 16, 16, 8, wmma::precision::tf32, wmma::col_major> FragB;

__global__ __launch_bounds__(NTHR, 1) void tc_gemm(
    const float* __restrict__ A, const float* __restrict__ B,
    float* __restrict__ C, int strideA, int strideB,
    int Klen, int Ncols, size_t csplit)
{
    extern __shared__ __align__(16) char smem[];
    float* sf = reinterpret_cast<float*>(smem);
    const uint32_t sb = smem_u32(smem);

    const int tid  = threadIdx.x;
    const int warp = tid >> 5;
    const int bm0  = blockIdx.y * BM;
    const int bn0  = blockIdx.x * BN;
    const int koff = blockIdx.z * Klen;
    C += (size_t)blockIdx.z * csplit;
    const int wm0 = (warp >> 1) * 64;    // 4 warp rows
    const int wn0 = (warp & 1) * 64;     // 2 warp cols
    const int NKB = Klen / BK;

    wmma::fragment<wmma::accumulator, 16, 16, 8, float> acc[WMI][WNI];
    #pragma unroll
    for (int i = 0; i < WMI; i++)
        #pragma unroll
        for (int j = 0; j < WNI; j++)
            wmma::fill_fragment(acc[i][j], 0.f);

    const float* Abase = A + (size_t)bm0 * strideA + koff;
    const float* Bbase = B + (size_t)bn0 * strideB + koff;

    const int lr = tid >> 3;             // 0..31 (32 rows per pass)
    const int lc = tid & 7;              // 16B chunk within 128B of K data

    auto load_stage = [&](int s, int kb) {
        const uint32_t abase = sb + s * STAGE_B;
        const uint32_t bbase = abase + A_STAGE_B;
        const float* Ag = Abase + (size_t)kb * BK;
        const float* Bg = Bbase + (size_t)kb * BK;
        #pragma unroll
        for (int i = 0; i < 8; i++) {    // A: 256 rows
            const int row = lr + i * 32;
            cp16(abase + row * (BKP * 4) + lc * 16, Ag + (size_t)row * strideA + lc * 4);
        }
        #pragma unroll
        for (int i = 0; i < 4; i++) {    // B: 128 rows
            const int row = lr + i * 32;
            cp16(bbase + row * (BKP * 4) + lc * 16, Bg + (size_t)row * strideB + lc * 4);
        }
    };

    #pragma unroll
    for (int p = 0; p < STAGES - 1; p++) { load_stage(p, p); CP_COMMIT(); }

    FragA af[2][WMI];
    FragB bf[2][WNI];

    for (int kb = 0; kb < NKB; kb++) {
        CP_WAIT2();                  // stage kb resident
        __syncthreads();             // all warps done reading stage (kb-1)%STAGES
        const int jn = kb + (STAGES - 1);
        if (jn < NKB) load_stage(jn % STAGES, jn);
        CP_COMMIT();                 // uniform group numbering (empty at tail)

        const int s = kb % STAGES;
        float* As = sf + (size_t)s * (STAGE_B / 4);
        float* Bs = As + (A_STAGE_B / 4);

        // prefetch ks=0 fragments into buffer 0
        #pragma unroll
        for (int i = 0; i < WMI; i++)
            wmma::load_matrix_sync(af[0][i], As + (size_t)(wm0 + i * 16) * BKP, BKP);
        #pragma unroll
        for (int j = 0; j < WNI; j++)
            wmma::load_matrix_sync(bf[0][j], Bs + (size_t)(wn0 + j * 16) * BKP, BKP);

        #pragma unroll
        for (int ks = 0; ks < BK / 8; ++ks) {
            const int cur = ks & 1, nxt = cur ^ 1;
            if (ks < BK / 8 - 1) {   // prefetch ks+1 while computing ks
                #pragma unroll
                for (int i = 0; i < WMI; i++)
                    wmma::load_matrix_sync(af[nxt][i],
                        As + (size_t)(wm0 + i * 16) * BKP + (ks + 1) * 8, BKP);
                #pragma unroll
                for (int j = 0; j < WNI; j++)
                    wmma::load_matrix_sync(bf[nxt][j],
                        Bs + (size_t)(wn0 + j * 16) * BKP + (ks + 1) * 8, BKP);
            }
            #pragma unroll
            for (int i = 0; i < WMI; i++)
                #pragma unroll
                for (int j = 0; j < WNI; j++)
                    wmma::mma_sync(acc[i][j], af[cur][i], bf[cur][j], acc[i][j]);
        }
    }

    #pragma unroll
    for (int i = 0; i < WMI; i++)
        #pragma unroll
        for (int j = 0; j < WNI; j++)
            wmma::store_matrix_sync(
                &C[(size_t)(bm0 + wm0 + i * 16) * Ncols + (bn0 + wn0 + j * 16)],
                acc[i][j], Ncols, wmma::mem_row_major);
}

// ---------------- pre/post kernels ----------------
__global__ void rowsum_rsqrt(const float* __restrict__ mat, float* __restrict__ out) {
    const int row = blockIdx.x;
    const float4* p = reinterpret_cast<const float4*>(mat + (size_t)row * N_NODES);
    float s = 0.f;
    for (int j = threadIdx.x; j < N_NODES / 4; j += blockDim.x) {
        float4 v = p[j]; s += (v.x + v.y) + (v.z + v.w);
    }
    #pragma unroll
    for (int o = 16; o > 0; o >>= 1) s += __shfl_down_sync(0xffffffffu, s, o);
    __shared__ float red[8];
    const int lane = threadIdx.x & 31, w = threadIdx.x >> 5;
    if (lane == 0) red[w] = s;
    __syncthreads();
    if (w == 0) {
        s = (lane < 8) ? red[lane] : 0.f;
        #pragma unroll
        for (int o = 4; o > 0; o >>= 1) s += __shfl_down_sync(0xffffffffu, s, o);
        if (lane == 0) out[row] = (s > 0.f) ? rsqrtf(s) : 0.f;
    }
}

// Asc[i,j] = rna(inv[i]*edge[i,j]*inv[j]); asum[i] = rowsum(Asc[i,:]) (fused)
__global__ void norm_edge_rowsum(const float* __restrict__ edge, const float* __restrict__ inv,
                                 float* __restrict__ out, float* __restrict__ asum) {
    const int row = blockIdx.x;
    const float s = inv[row];
    const float4* p  = reinterpret_cast<const float4*>(edge + (size_t)row * N_NODES);
    const float4* iv = reinterpret_cast<const float4*>(inv);
    float4* q = reinterpret_cast<float4*>(out + (size_t)row * N_NODES);
    float acc = 0.f;
    for (int j = threadIdx.x; j < N_NODES / 4; j += blockDim.x) {
        float4 v = p[j];
        float4 w = iv[j];
        float4 o = make_float4(f2tf32(s * v.x * w.x), f2tf32(s * v.y * w.y),
                               f2tf32(s * v.z * w.z), f2tf32(s * v.w * w.w));
        q[j] = o;
        acc += (o.x + o.y) + (o.z + o.w);
    }
    #pragma unroll
    for (int o = 16; o > 0; o >>= 1) acc += __shfl_down_sync(0xffffffffu, acc, o);
    __shared__ float red[8];
    const int lane = threadIdx.x & 31, w = threadIdx.x >> 5;
    if (lane == 0) red[w] = acc;
    __syncthreads();
    if (w == 0) {
        acc = (lane < 8) ? red[lane] : 0.f;
        #pragma unroll
        for (int o = 4; o > 0; o >>= 1) acc += __shfl_down_sync(0xffffffffu, acc, o);
        if (lane == 0) asum[row] = acc;
    }
}

__global__ void conv_rna(const float* __restrict__ in, float* __restrict__ out) {
    const size_t i = ((size_t)blockIdx.x * blockDim.x + threadIdx.x) * 4;
    float4 v = *reinterpret_cast<const float4*>(in + i);
    float4 o = make_float4(f2tf32(v.x), f2tf32(v.y), f2tf32(v.z), f2tf32(v.w));
    *reinterpret_cast<float4*>(out + i) = o;
}

__global__ void epi_rna(const float* __restrict__ in, float* __restrict__ out) {
    const size_t i = ((size_t)blockIdx.x * blockDim.x + threadIdx.x) * 4;
    float4 v = *reinterpret_cast<const float4*>(in + i);
    float4 o = make_float4(f2tf32(v.x), f2tf32(v.y), f2tf32(v.z), f2tf32(v.w));
    *reinterpret_cast<float4*>(out + i) = o;
}

// XT[c, n] = rna(X[n, c]); X is [N_NODES, IN_C]
__global__ void transpose_x_rna(const float* __restrict__ X, float* __restrict__ XT) {
    __shared__ float t[32][33];
    const int bx = blockIdx.x * 32, by = blockIdx.y * 32;
    const int x = threadIdx.x, y = threadIdx.y;   // 32 x 8
    #pragma unroll
    for (int yy = y; yy < 32; yy += 8)
        t[yy][x] = X[(size_t)(by + yy) * IN_C + bx + x];
    __syncthreads();
    #pragma unroll
    for (int yy = y; yy < 32; yy += 8)
        XT[(size_t)(bx + yy) * N_NODES + by + x] = f2tf32(t[x][yy]);
}

// outT[n, m] = rna(D0[m,n] + D1[m,n]); D is [M, Ncols]
__global__ void epi_transpose_sum2_rna(const float* __restrict__ D0, const float* __restrict__ D1,
                                       float* __restrict__ outT, int M, int Ncols) {
    __shared__ float t[32][33];
    const int bx = blockIdx.x * 32, by = blockIdx.y * 32;
    const int x = threadIdx.x, y = threadIdx.y;   // 32 x 8
    #pragma unroll
    for (int yy = y; yy < 32; yy += 8) {
        const size_t idx = (size_t)(by + yy) * Ncols + bx + x;
        t[yy][x] = D0[idx] + D1[idx];
    }
    __syncthreads();
    #pragma unroll
    for (int yy = y; yy < 32; yy += 8)
        outT[(size_t)(bx + yy) * M + by + x] = f2tf32(t[x][yy]);
}

// H[m,j] = rna(relu(C[m,j] + asum[m]*b1[j]))
__global__ void epi_relu_biasrow_rna(const float* __restrict__ C, const float* __restrict__ asum,
                                     const float* __restrict__ bias, float* __restrict__ out,
                                     int Ncols) {
    const size_t i = (size_t)blockIdx.x * blockDim.x + threadIdx.x;    // float4 idx
    const int m  = (int)(i / (Ncols / 4));
    const int j4 = (int)(i % (Ncols / 4)) * 4;
    const float a = __ldg(asum + m);
    float4 c = *reinterpret_cast<const float4*>(C + (size_t)m * Ncols + j4);
    float4 b = *reinterpret_cast<const float4*>(bias + j4);
    float4 o = make_float4(f2tf32(fmaxf(c.x + a * b.x, 0.f)),
                           f2tf32(fmaxf(c.y + a * b.y, 0.f)),
                           f2tf32(fmaxf(c.z + a * b.z, 0.f)),
                           f2tf32(fmaxf(c.w + a * b.w, 0.f)));
    *reinterpret_cast<float4*>(out + (size_t)m * Ncols + j4) = o;
}

// out[m,j] = relu(C0[m,j] + C1[m,j] + asum[m]*b2[j])  (final, no rounding)
__global__ void epi_relu_biasrow_sum2(const float* __restrict__ C0, const float* __restrict__ C1,
                                      const float* __restrict__ asum, const float* __restrict__ bias,
                                      float* __restrict__ out, int Ncols) {
    const size_t i = (size_t)blockIdx.x * blockDim.x + threadIdx.x;
    const int m  = (int)(i / (Ncols / 4));
    const int j4 = (int)(i % (Ncols / 4)) * 4;
    const float a = __ldg(asum + m);
    const size_t off = (size_t)m * Ncols + j4;
    float4 c0 = *reinterpret_cast<const float4*>(C0 + off);
    float4 c1 = *reinterpret_cast<const float4*>(C1 + off);
    float4 b  = *reinterpret_cast<const float4*>(bias + j4);
    float4 o = make_float4(fmaxf(c0.x + c1.x + a * b.x, 0.f),
                           fmaxf(c0.y + c1.y + a * b.y, 0.f),
                           fmaxf(c0.z + c1.z + a * b.z, 0.f),
                           fmaxf(c0.w + c1.w + a * b.w, 0.f));
    *reinterpret_cast<float4*>(out + off) = o;
}

// ---------------- launch ----------------
extern "C" void kernel_launch(void* const* d_in, const int* in_sizes, int n_in,
                              void* d_out, int out_size) {
    const float* point = (const float*)d_in[0];
    const float* edge  = (const float*)d_in[1];
    const float* W1    = (const float*)d_in[2];
    const float* b1    = (const float*)d_in[3];
    const float* W2    = (const float*)d_in[4];
    const float* b2    = (const float*)d_in[5];
    float* out = (float*)d_out;

    float *inv, *asum, *Asc, *XT, *W1r, *W2r, *G, *C, *H, *OsT;
    cudaGetSymbolAddress((void**)&inv,  g_inv);
    cudaGetSymbolAddress((void**)&asum, g_asum);
    cudaGetSymbolAddress((void**)&Asc,  g_edge);
    cudaGetSymbolAddress((void**)&XT,   g_XT);
    cudaGetSymbolAddress((void**)&W1r,  g_W1r);
    cudaGetSymbolAddress((void**)&W2r,  g_W2r);
    cudaGetSymbolAddress((void**)&G,    g_G);
    cudaGetSymbolAddress((void**)&C,    g_C);
    cudaGetSymbolAddress((void**)&H,    g_H);
    cudaGetSymbolAddress((void**)&OsT,  g_OsT);

    cudaFuncSetAttribute(tc_gemm, cudaFuncAttributeMaxDynamicSharedMemorySize, SMEM_GEMM);

    const size_t SPLIT = (size_t)N_NODES * OUT_C;   // split-K partial buffer stride

    // #1..#3: normalization + X transpose (tc_gemm_a stays launch #4 for ncu)
    rowsum_rsqrt<<<N_NODES, 256>>>(edge, inv);
    norm_edge_rowsum<<<N_NODES, 256>>>(edge, inv, Asc, asum);
    transpose_x_rna<<<dim3(IN_C / 32, N_NODES / 32), dim3(32, 8)>>>(point, XT);

    // #4 GEMM_a: G = Asc @ X  [8192, 512]  (68.7 GF; 128 CTAs, 1 wave)
    tc_gemm<<<dim3(IN_C / BN, N_NODES / BM, 1), NTHR, SMEM_GEMM>>>(
        Asc, XT, G, N_NODES, N_NODES, N_NODES, IN_C, 0);

    // weight rounding (independent of GEMM_a; placed after to keep launch order)
    conv_rna<<<(HID_C * IN_C / 4) / 256, 256>>>(W1, W1r);
    conv_rna<<<(OUT_C * HID_C / 4) / 256, 256>>>(W2, W2r);
    epi_rna<<<(N_NODES * IN_C / 4) / 256, 256>>>(G, G);

    // GEMM_b: C = G @ W1^T  [8192, 1024]  (256 CTAs)
    tc_gemm<<<dim3(HID_C / BN, N_NODES / BM, 1), NTHR, SMEM_GEMM>>>(
        G, W1r, C, IN_C, IN_C, IN_C, HID_C, 0);
    epi_relu_biasrow_rna<<<(N_NODES * HID_C / 4) / 256, 256>>>(C, asum, b1, H, HID_C);

    // GEMM_c: split-K=2 -> D0,D1 in g_G  [8192, 256] each  (128 CTAs)
    tc_gemm<<<dim3(OUT_C / BN, N_NODES / BM, 2), NTHR, SMEM_GEMM>>>(
        H, W2r, G, HID_C, HID_C, HID_C / 2, OUT_C, SPLIT);
    epi_transpose_sum2_rna<<<dim3(OUT_C / 32, N_NODES / 32), dim3(32, 8)>>>(
        G, G + SPLIT, OsT, N_NODES, OUT_C);

    // GEMM_d: split-K=2 -> C0,C1 in g_C  [8192, 256] each  (128 CTAs)
    tc_gemm<<<dim3(OUT_C / BN, N_NODES / BM, 2), NTHR, SMEM_GEMM>>>(
        Asc, OsT, C, N_NODES, N_NODES, N_NODES / 2, OUT_C, SPLIT);
    epi_relu_biasrow_sum2<<<(N_NODES * OUT_C / 4) / 256, 256>>>(C, C + SPLIT, asum, b2, out, OUT_C);
}

// round 11
// speedup vs baseline: 3.5215x; 3.2339x over previous
#include <cuda_runtime.h>
#include <cuda_fp16.h>
#include <mma.h>
#include <cstdint>
#include <cstddef>

using namespace nvcuda;

#define N_NODES 8192
#define IN_C    512
#define HID_C   1024
#define OUT_C   256

#define SCALE_S 4096.0f
#define INV_S   (1.0f / 4096.0f)

// ---------------- scratch (static device arrays; no allocations) ----------------
__device__ float  g_inv [N_NODES];
__device__ float  g_asum[N_NODES];                       // rowsum of Â (unscaled)
__device__ __half g_Ah  [(size_t)N_NODES * N_NODES];     // fp16(S * Â)  (128 MB)
__device__ __half g_XTh [(size_t)IN_C * N_NODES];        // fp16(X^T)
__device__ __half g_W1h [(size_t)HID_C * IN_C];
__device__ __half g_W2h [(size_t)OUT_C * HID_C];
__device__ __half g_Gh  [(size_t)N_NODES * IN_C];        // fp16(Â@X)
__device__ __half g_Hh  [(size_t)N_NODES * HID_C];       // fp16(relu hidden)
__device__ __half g_OsTh[(size_t)OUT_C * N_NODES];       // fp16((H@W2^T)^T)
__device__ float  g_G   [(size_t)N_NODES * IN_C];        // GEMM_a out; GEMM_c splits
__device__ float  g_C   [(size_t)N_NODES * HID_C];       // GEMM_b out; GEMM_d splits

__device__ __forceinline__ uint32_t smem_u32(const void* p) {
    uint32_t a;
    asm("{ .reg .u64 t; cvta.to.shared.u64 t, %1; cvt.u32.u64 %0, t; }" : "=r"(a) : "l"(p));
    return a;
}
__device__ __forceinline__ void cp16(uint32_t dst, const void* src) {
    asm volatile("cp.async.cg.shared.global [%0], [%1], 16;" :: "r"(dst), "l"(src));
}
#define CP_COMMIT() asm volatile("cp.async.commit_group;" ::: "memory")
#define CP_WAIT2()  asm volatile("cp.async.wait_group 2;" ::: "memory")

// ---- fp16 wmma GEMM: 256x128 block, 256 thr, 8 warps of 64x64 (4x2 grid),
// ---- 4-stage cp.async. C[M,Ncols](fp32) = A[M,Klen] @ B[Ncols,Klen]^T, both fp16 K-major.
// blockIdx.z = split-K slice: koff = z*Klen, C += z*csplit.
constexpr int NTHR = 256;
constexpr int BM = 256, BN = 128, BK = 64;                // BK halves = 128 B/row
constexpr int BKP = 72;                                   // 144 B/row padded
constexpr int STAGES = 4;
constexpr int A_STAGE_B = BM * BKP * 2;                   // 36864
constexpr int STAGE_B   = (BM + BN) * BKP * 2;            // 55296
constexpr int SMEM_GEMM = STAGES * STAGE_B;               // 221184
constexpr int WMI = 4, WNI = 4;                           // 64x64 warp tile

__global__ __launch_bounds__(NTHR, 1) void tc_gemm(
    const __half* __restrict__ A, const __half* __restrict__ B,
    float* __restrict__ C, int strideA, int strideB,
    int Klen, int Ncols, size_t csplit)
{
    extern __shared__ __align__(16) char smem[];
    __half* sh = reinterpret_cast<__half*>(smem);
    const uint32_t sb = smem_u32(smem);

    const int tid  = threadIdx.x;
    const int warp = tid >> 5;
    const int bm0  = blockIdx.y * BM;
    const int bn0  = blockIdx.x * BN;
    const int koff = blockIdx.z * Klen;
    C += (size_t)blockIdx.z * csplit;
    const int wm0 = (warp >> 1) * 64;    // 4 warp rows
    const int wn0 = (warp & 1) * 64;     // 2 warp cols
    const int NKB = Klen / BK;

    wmma::fragment<wmma::accumulator, 16, 16, 16, float> acc[WMI][WNI];
    #pragma unroll
    for (int i = 0; i < WMI; i++)
        #pragma unroll
        for (int j = 0; j < WNI; j++)
            wmma::fill_fragment(acc[i][j], 0.f);

    const __half* Abase = A + (size_t)bm0 * strideA + koff;
    const __half* Bbase = B + (size_t)bn0 * strideB + koff;

    const int lr = tid >> 3;             // 0..31 (32 rows per pass)
    const int lc = tid & 7;              // 16B chunk (8 halves) within 128B row

    auto load_stage = [&](int s, int kb) {
        const uint32_t abase = sb + s * STAGE_B;
        const uint32_t bbase = abase + A_STAGE_B;
        const __half* Ag = Abase + (size_t)kb * BK;
        const __half* Bg = Bbase + (size_t)kb * BK;
        #pragma unroll
        for (int i = 0; i < 8; i++) {    // A: 256 rows
            const int row = lr + i * 32;
            cp16(abase + row * (BKP * 2) + lc * 16, Ag + (size_t)row * strideA + lc * 8);
        }
        #pragma unroll
        for (int i = 0; i < 4; i++) {    // B: 128 rows
            const int row = lr + i * 32;
            cp16(bbase + row * (BKP * 2) + lc * 16, Bg + (size_t)row * strideB + lc * 8);
        }
    };

    #pragma unroll
    for (int p = 0; p < STAGES - 1; p++) { load_stage(p, p); CP_COMMIT(); }

    for (int kb = 0; kb < NKB; kb++) {
        CP_WAIT2();                  // stage kb resident
        __syncthreads();             // all warps done reading stage (kb-1)%STAGES
        const int jn = kb + (STAGES - 1);
        if (jn < NKB) load_stage(jn % STAGES, jn);
        CP_COMMIT();                 // uniform group numbering (empty at tail)

        const int s = kb % STAGES;
        __half* As = sh + (size_t)s * (STAGE_B / 2);
        __half* Bs = As + (A_STAGE_B / 2);

        #pragma unroll
        for (int ks = 0; ks < BK / 16; ++ks) {
            wmma::fragment<wmma::matrix_a, 16, 16, 16, __half, wmma::row_major> af[WMI];
            wmma::fragment<wmma::matrix_b, 16, 16, 16, __half, wmma::col_major> bf[WNI];
            #pragma unroll
            for (int i = 0; i < WMI; i++)
                wmma::load_matrix_sync(af[i], As + (size_t)(wm0 + i * 16) * BKP + ks * 16, BKP);
            #pragma unroll
            for (int j = 0; j < WNI; j++)
                wmma::load_matrix_sync(bf[j], Bs + (size_t)(wn0 + j * 16) * BKP + ks * 16, BKP);
            #pragma unroll
            for (int i = 0; i < WMI; i++)
                #pragma unroll
                for (int j = 0; j < WNI; j++)
                    wmma::mma_sync(acc[i][j], af[i], bf[j], acc[i][j]);
        }
    }

    #pragma unroll
    for (int i = 0; i < WMI; i++)
        #pragma unroll
        for (int j = 0; j < WNI; j++)
            wmma::store_matrix_sync(
                &C[(size_t)(bm0 + wm0 + i * 16) * Ncols + (bn0 + wn0 + j * 16)],
                acc[i][j], Ncols, wmma::mem_row_major);
}

// ---------------- pre/post kernels ----------------
__global__ void rowsum_rsqrt(const float* __restrict__ mat, float* __restrict__ out) {
    const int row = blockIdx.x;
    const float4* p = reinterpret_cast<const float4*>(mat + (size_t)row * N_NODES);
    float s = 0.f;
    for (int j = threadIdx.x; j < N_NODES / 4; j += blockDim.x) {
        float4 v = p[j]; s += (v.x + v.y) + (v.z + v.w);
    }
    #pragma unroll
    for (int o = 16; o > 0; o >>= 1) s += __shfl_down_sync(0xffffffffu, s, o);
    __shared__ float red[8];
    const int lane = threadIdx.x & 31, w = threadIdx.x >> 5;
    if (lane == 0) red[w] = s;
    __syncthreads();
    if (w == 0) {
        s = (lane < 8) ? red[lane] : 0.f;
        #pragma unroll
        for (int o = 4; o > 0; o >>= 1) s += __shfl_down_sync(0xffffffffu, s, o);
        if (lane == 0) out[row] = (s > 0.f) ? rsqrtf(s) : 0.f;
    }
}

// Ah[i,j] = fp16(S * inv[i]*edge[i,j]*inv[j]); asum[i] = (1/S) * rowsum(fp16 values)
__global__ void norm_edge_rowsum(const float* __restrict__ edge, const float* __restrict__ inv,
                                 __half* __restrict__ outh, float* __restrict__ asum) {
    const int row = blockIdx.x;
    const float s = inv[row] * SCALE_S;
    const float4* p  = reinterpret_cast<const float4*>(edge + (size_t)row * N_NODES);
    const float4* iv = reinterpret_cast<const float4*>(inv);
    __half2* q = reinterpret_cast<__half2*>(outh + (size_t)row * N_NODES);
    float acc = 0.f;
    for (int j = threadIdx.x; j < N_NODES / 4; j += blockDim.x) {
        float4 v = p[j];
        float4 w = iv[j];
        __half2 h01 = __floats2half2_rn(s * v.x * w.x, s * v.y * w.y);
        __half2 h23 = __floats2half2_rn(s * v.z * w.z, s * v.w * w.w);
        q[j * 2]     = h01;
        q[j * 2 + 1] = h23;
        float2 f01 = __half22float2(h01), f23 = __half22float2(h23);
        acc += (f01.x + f01.y) + (f23.x + f23.y);
    }
    #pragma unroll
    for (int o = 16; o > 0; o >>= 1) acc += __shfl_down_sync(0xffffffffu, acc, o);
    __shared__ float red[8];
    const int lane = threadIdx.x & 31, w = threadIdx.x >> 5;
    if (lane == 0) red[w] = acc;
    __syncthreads();
    if (w == 0) {
        acc = (lane < 8) ? red[lane] : 0.f;
        #pragma unroll
        for (int o = 4; o > 0; o >>= 1) acc += __shfl_down_sync(0xffffffffu, acc, o);
        if (lane == 0) asum[row] = acc * INV_S;
    }
}

// generic fp32 -> fp16 (4 per thread)
__global__ void conv_h(const float* __restrict__ in, __half* __restrict__ out) {
    const size_t i = ((size_t)blockIdx.x * blockDim.x + threadIdx.x) * 4;
    float4 v = *reinterpret_cast<const float4*>(in + i);
    __half2* q = reinterpret_cast<__half2*>(out + i);
    q[0] = __floats2half2_rn(v.x, v.y);
    q[1] = __floats2half2_rn(v.z, v.w);
}

// Gh = fp16(G * INV_S)   (GEMM_a output is scaled by S)
__global__ void epi_scale_h(const float* __restrict__ in, __half* __restrict__ out) {
    const size_t i = ((size_t)blockIdx.x * blockDim.x + threadIdx.x) * 4;
    float4 v = *reinterpret_cast<const float4*>(in + i);
    __half2* q = reinterpret_cast<__half2*>(out + i);
    q[0] = __floats2half2_rn(v.x * INV_S, v.y * INV_S);
    q[1] = __floats2half2_rn(v.z * INV_S, v.w * INV_S);
}

// XTh[c, n] = fp16(X[n, c]); X is [N_NODES, IN_C]
__global__ void transpose_x_h(const float* __restrict__ X, __half* __restrict__ XT) {
    __shared__ float t[32][33];
    const int bx = blockIdx.x * 32, by = blockIdx.y * 32;
    const int x = threadIdx.x, y = threadIdx.y;   // 32 x 8
    #pragma unroll
    for (int yy = y; yy < 32; yy += 8)
        t[yy][x] = X[(size_t)(by + yy) * IN_C + bx + x];
    __syncthreads();
    #pragma unroll
    for (int yy = y; yy < 32; yy += 8)
        XT[(size_t)(bx + yy) * N_NODES + by + x] = __float2half_rn(t[x][yy]);
}

// outT[n, m] = fp16(D0[m,n] + D1[m,n]); D is [M, Ncols]
__global__ void epi_transpose_sum2_h(const float* __restrict__ D0, const float* __restrict__ D1,
                                     __half* __restrict__ outT, int M, int Ncols) {
    __shared__ float t[32][33];
    const int bx = blockIdx.x * 32, by = blockIdx.y * 32;
    const int x = threadIdx.x, y = threadIdx.y;   // 32 x 8
    #pragma unroll
    for (int yy = y; yy < 32; yy += 8) {
        const size_t idx = (size_t)(by + yy) * Ncols + bx + x;
        t[yy][x] = D0[idx] + D1[idx];
    }
    __syncthreads();
    #pragma unroll
    for (int yy = y; yy < 32; yy += 8)
        outT[(size_t)(bx + yy) * M + by + x] = __float2half_rn(t[x][yy]);
}

// Hh[m,j] = fp16(relu(C[m,j] + asum[m]*b1[j]))
__global__ void epi_relu_biasrow_h(const float* __restrict__ C, const float* __restrict__ asum,
                                   const float* __restrict__ bias, __half* __restrict__ out,
                                   int Ncols) {
    const size_t i = (size_t)blockIdx.x * blockDim.x + threadIdx.x;    // float4 idx
    const int m  = (int)(i / (Ncols / 4));
    const int j4 = (int)(i % (Ncols / 4)) * 4;
    const float a = __ldg(asum + m);
    float4 c = *reinterpret_cast<const float4*>(C + (size_t)m * Ncols + j4);
    float4 b = *reinterpret_cast<const float4*>(bias + j4);
    __half2* q = reinterpret_cast<__half2*>(out + (size_t)m * Ncols + j4);
    q[0] = __floats2half2_rn(fmaxf(c.x + a * b.x, 0.f), fmaxf(c.y + a * b.y, 0.f));
    q[1] = __floats2half2_rn(fmaxf(c.z + a * b.z, 0.f), fmaxf(c.w + a * b.w, 0.f));
}

// out[m,j] = relu((C0+C1)*INV_S + asum[m]*b2[j])  (final, fp32)
__global__ void epi_relu_biasrow_sum2(const float* __restrict__ C0, const float* __restrict__ C1,
                                      const float* __restrict__ asum, const float* __restrict__ bias,
                                      float* __restrict__ out, int Ncols) {
    const size_t i = (size_t)blockIdx.x * blockDim.x + threadIdx.x;
    const int m  = (int)(i / (Ncols / 4));
    const int j4 = (int)(i % (Ncols / 4)) * 4;
    const float a = __ldg(asum + m);
    const size_t off = (size_t)m * Ncols + j4;
    float4 c0 = *reinterpret_cast<const float4*>(C0 + off);
    float4 c1 = *reinterpret_cast<const float4*>(C1 + off);
    float4 b  = *reinterpret_cast<const float4*>(bias + j4);
    float4 o = make_float4(fmaxf((c0.x + c1.x) * INV_S + a * b.x, 0.f),
                           fmaxf((c0.y + c1.y) * INV_S + a * b.y, 0.f),
                           fmaxf((c0.z + c1.z) * INV_S + a * b.z, 0.f),
                           fmaxf((c0.w + c1.w) * INV_S + a * b.w, 0.f));
    *reinterpret_cast<float4*>(out + off) = o;
}

// ---------------- launch ----------------
extern "C" void kernel_launch(void* const* d_in, const int* in_sizes, int n_in,
                              void* d_out, int out_size) {
    const float* point = (const float*)d_in[0];
    const float* edge  = (const float*)d_in[1];
    const float* W1    = (const float*)d_in[2];
    const float* b1    = (const float*)d_in[3];
    const float* W2    = (const float*)d_in[4];
    const float* b2    = (const float*)d_in[5];
    float* out = (float*)d_out;

    float *inv, *asum, *G, *C;
    __half *Ah, *XTh, *W1h, *W2h, *Gh, *Hh, *OsTh;
    cudaGetSymbolAddress((void**)&inv,  g_inv);
    cudaGetSymbolAddress((void**)&asum, g_asum);
    cudaGetSymbolAddress((void**)&Ah,   g_Ah);
    cudaGetSymbolAddress((void**)&XTh,  g_XTh);
    cudaGetSymbolAddress((void**)&W1h,  g_W1h);
    cudaGetSymbolAddress((void**)&W2h,  g_W2h);
    cudaGetSymbolAddress((void**)&Gh,   g_Gh);
    cudaGetSymbolAddress((void**)&Hh,   g_Hh);
    cudaGetSymbolAddress((void**)&OsTh, g_OsTh);
    cudaGetSymbolAddress((void**)&G,    g_G);
    cudaGetSymbolAddress((void**)&C,    g_C);

    cudaFuncSetAttribute(tc_gemm, cudaFuncAttributeMaxDynamicSharedMemorySize, SMEM_GEMM);

    const size_t SPLIT = (size_t)N_NODES * OUT_C;   // split-K partial buffer stride

    // #1..#3: normalization + X transpose (tc_gemm_a stays launch #4 for ncu)
    rowsum_rsqrt<<<N_NODES, 256>>>(edge, inv);
    norm_edge_rowsum<<<N_NODES, 256>>>(edge, inv, Ah, asum);
    transpose_x_h<<<dim3(IN_C / 32, N_NODES / 32), dim3(32, 8)>>>(point, XTh);

    // #4 GEMM_a: G = (S*Â) @ X  [8192, 512]  fp32 out (128 CTAs, 1 wave)
    tc_gemm<<<dim3(IN_C / BN, N_NODES / BM, 1), NTHR, SMEM_GEMM>>>(
        Ah, XTh, G, N_NODES, N_NODES, N_NODES, IN_C, 0);

    // weight rounding (independent; after GEMM_a to keep launch order)
    conv_h<<<(HID_C * IN_C / 4) / 256, 256>>>(W1, W1h);
    conv_h<<<(OUT_C * HID_C / 4) / 256, 256>>>(W2, W2h);
    epi_scale_h<<<(N_NODES * IN_C / 4) / 256, 256>>>(G, Gh);   // Gh = fp16(G/S)

    // GEMM_b: C = G @ W1^T  [8192, 1024]  (256 CTAs)
    tc_gemm<<<dim3(HID_C / BN, N_NODES / BM, 1), NTHR, SMEM_GEMM>>>(
        Gh, W1h, C, IN_C, IN_C, IN_C, HID_C, 0);
    epi_relu_biasrow_h<<<(N_NODES * HID_C / 4) / 256, 256>>>(C, asum, b1, Hh, HID_C);

    // GEMM_c: split-K=2 -> D0,D1 in g_G  [8192, 256] each  (128 CTAs)
    tc_gemm<<<dim3(OUT_C / BN, N_NODES / BM, 2), NTHR, SMEM_GEMM>>>(
        Hh, W2h, G, HID_C, HID_C, HID_C / 2, OUT_C, SPLIT);
    epi_transpose_sum2_h<<<dim3(OUT_C / 32, N_NODES / 32), dim3(32, 8)>>>(
        G, G + SPLIT, OsTh, N_NODES, OUT_C);

    // GEMM_d: split-K=2 -> C0,C1 in g_C  [8192, 256] each  (128 CTAs)
    tc_gemm<<<dim3(OUT_C / BN, N_NODES / BM, 2), NTHR, SMEM_GEMM>>>(
        Ah, OsTh, C, N_NODES, N_NODES, N_NODES / 2, OUT_C, SPLIT);
    epi_relu_biasrow_sum2<<<(N_NODES * OUT_C / 4) / 256, 256>>>(C, C + SPLIT, asum, b2, out, OUT_C);
}

// round 12
// speedup vs baseline: 3.5788x; 1.0163x over previous
#include <cuda_runtime.h>
#include <cuda_fp16.h>
#include <mma.h>
#include <cstdint>
#include <cstddef>

using namespace nvcuda;

#define N_NODES 8192
#define IN_C    512
#define HID_C   1024
#define OUT_C   256

#define SCALE_S 4096.0f
#define INV_S   (1.0f / 4096.0f)

// ---------------- scratch (static device arrays; no allocations) ----------------
__device__ float  g_inv [N_NODES];
__device__ float  g_asum[N_NODES];                       // rowsum of Â (unscaled)
__device__ __half g_Ah  [(size_t)N_NODES * N_NODES];     // fp16(S * Â)  (128 MB)
__device__ __half g_XTh [(size_t)IN_C * N_NODES];        // fp16(X^T)
__device__ __half g_W1h [(size_t)HID_C * IN_C];
__device__ __half g_W2h [(size_t)OUT_C * HID_C];
__device__ __half g_Gh  [(size_t)N_NODES * IN_C];        // fp16(Â@X)
__device__ __half g_Hh  [(size_t)N_NODES * HID_C];       // fp16(relu hidden)
__device__ __half g_OsTh[(size_t)OUT_C * N_NODES];       // fp16((H@W2^T)^T)
__device__ float  g_G   [(size_t)N_NODES * IN_C];        // GEMM_a out; GEMM_c splits
__device__ float  g_C   [(size_t)N_NODES * HID_C];       // GEMM_b out; GEMM_d splits

__device__ __forceinline__ uint32_t smem_u32(const void* p) {
    uint32_t a;
    asm("{ .reg .u64 t; cvta.to.shared.u64 t, %1; cvt.u32.u64 %0, t; }" : "=r"(a) : "l"(p));
    return a;
}
__device__ __forceinline__ void cp16(uint32_t dst, const void* src) {
    asm volatile("cp.async.cg.shared.global [%0], [%1], 16;" :: "r"(dst), "l"(src));
}
#define CP_COMMIT() asm volatile("cp.async.commit_group;" ::: "memory")
#define CP_WAIT1()  asm volatile("cp.async.wait_group 1;" ::: "memory")

// ---- fp16 wmma GEMM: 128x128 block, 256 thr, 8 warps of 32x64 (4x2 grid),
// ---- 3-stage cp.async, 2 CTAs/SM (independent barrier domains decouple
// ---- LDS-phase / MMA-phase so the tensor pipe stays fed).
// C[M,Ncols](fp32) = A[M,Klen] @ B[Ncols,Klen]^T, both fp16 K-major.
// blockIdx.z = split-K slice: koff = z*Klen, C += z*csplit.
constexpr int NTHR = 256;
constexpr int BM = 128, BN = 128, BK = 64;                // BK halves = 128 B/row
constexpr int BKP = 72;                                   // 144 B/row padded
constexpr int STAGES = 3;
constexpr int A_STAGE_B = BM * BKP * 2;                   // 18432
constexpr int STAGE_B   = (BM + BN) * BKP * 2;            // 36864
constexpr int SMEM_GEMM = STAGES * STAGE_B;               // 110592 (x2 CTAs = 221184/SM)
constexpr int WMI = 2, WNI = 4;                           // 32x64 warp tile

__global__ __launch_bounds__(NTHR, 2) void tc_gemm(
    const __half* __restrict__ A, const __half* __restrict__ B,
    float* __restrict__ C, int strideA, int strideB,
    int Klen, int Ncols, size_t csplit)
{
    extern __shared__ __align__(16) char smem[];
    __half* sh = reinterpret_cast<__half*>(smem);
    const uint32_t sb = smem_u32(smem);

    const int tid  = threadIdx.x;
    const int warp = tid >> 5;
    const int bm0  = blockIdx.y * BM;
    const int bn0  = blockIdx.x * BN;
    const int koff = blockIdx.z * Klen;
    C += (size_t)blockIdx.z * csplit;
    const int wm0 = (warp >> 1) * 32;    // 4 warp rows
    const int wn0 = (warp & 1) * 64;     // 2 warp cols
    const int NKB = Klen / BK;

    wmma::fragment<wmma::accumulator, 16, 16, 16, float> acc[WMI][WNI];
    #pragma unroll
    for (int i = 0; i < WMI; i++)
        #pragma unroll
        for (int j = 0; j < WNI; j++)
            wmma::fill_fragment(acc[i][j], 0.f);

    const __half* Abase = A + (size_t)bm0 * strideA + koff;
    const __half* Bbase = B + (size_t)bn0 * strideB + koff;

    const int lr = tid >> 3;             // 0..31 (32 rows per pass)
    const int lc = tid & 7;              // 16B chunk (8 halves) within 128B row

    auto load_stage = [&](int s, int kb) {
        const uint32_t abase = sb + s * STAGE_B;
        const uint32_t bbase = abase + A_STAGE_B;
        const __half* Ag = Abase + (size_t)kb * BK;
        const __half* Bg = Bbase + (size_t)kb * BK;
        #pragma unroll
        for (int i = 0; i < 4; i++) {    // A: 128 rows
            const int row = lr + i * 32;
            cp16(abase + row * (BKP * 2) + lc * 16, Ag + (size_t)row * strideA + lc * 8);
        }
        #pragma unroll
        for (int i = 0; i < 4; i++) {    // B: 128 rows
            const int row = lr + i * 32;
            cp16(bbase + row * (BKP * 2) + lc * 16, Bg + (size_t)row * strideB + lc * 8);
        }
    };

    #pragma unroll
    for (int p = 0; p < STAGES - 1; p++) { load_stage(p, p); CP_COMMIT(); }

    for (int kb = 0; kb < NKB; kb++) {
        CP_WAIT1();                  // stage kb resident (1 newer group may pend)
        __syncthreads();             // all warps done computing iter kb-1
        const int jn = kb + (STAGES - 1);
        if (jn < NKB) load_stage(jn % STAGES, jn);
        CP_COMMIT();                 // uniform group numbering (empty at tail)

        const int s = kb % STAGES;
        __half* As = sh + (size_t)s * (STAGE_B / 2);
        __half* Bs = As + (A_STAGE_B / 2);

        #pragma unroll
        for (int ks = 0; ks < BK / 16; ++ks) {
            wmma::fragment<wmma::matrix_a, 16, 16, 16, __half, wmma::row_major> af[WMI];
            wmma::fragment<wmma::matrix_b, 16, 16, 16, __half, wmma::col_major> bf[WNI];
            #pragma unroll
            for (int i = 0; i < WMI; i++)
                wmma::load_matrix_sync(af[i], As + (size_t)(wm0 + i * 16) * BKP + ks * 16, BKP);
            #pragma unroll
            for (int j = 0; j < WNI; j++)
                wmma::load_matrix_sync(bf[j], Bs + (size_t)(wn0 + j * 16) * BKP + ks * 16, BKP);
            #pragma unroll
            for (int i = 0; i < WMI; i++)
                #pragma unroll
                for (int j = 0; j < WNI; j++)
                    wmma::mma_sync(acc[i][j], af[i], bf[j], acc[i][j]);
        }
    }

    #pragma unroll
    for (int i = 0; i < WMI; i++)
        #pragma unroll
        for (int j = 0; j < WNI; j++)
            wmma::store_matrix_sync(
                &C[(size_t)(bm0 + wm0 + i * 16) * Ncols + (bn0 + wn0 + j * 16)],
                acc[i][j], Ncols, wmma::mem_row_major);
}

// ---------------- pre/post kernels ----------------
__global__ void rowsum_rsqrt(const float* __restrict__ mat, float* __restrict__ out) {
    const int row = blockIdx.x;
    const float4* p = reinterpret_cast<const float4*>(mat + (size_t)row * N_NODES);
    float s = 0.f;
    for (int j = threadIdx.x; j < N_NODES / 4; j += blockDim.x) {
        float4 v = p[j]; s += (v.x + v.y) + (v.z + v.w);
    }
    #pragma unroll
    for (int o = 16; o > 0; o >>= 1) s += __shfl_down_sync(0xffffffffu, s, o);
    __shared__ float red[8];
    const int lane = threadIdx.x & 31, w = threadIdx.x >> 5;
    if (lane == 0) red[w] = s;
    __syncthreads();
    if (w == 0) {
        s = (lane < 8) ? red[lane] : 0.f;
        #pragma unroll
        for (int o = 4; o > 0; o >>= 1) s += __shfl_down_sync(0xffffffffu, s, o);
        if (lane == 0) out[row] = (s > 0.f) ? rsqrtf(s) : 0.f;
    }
}

// Ah[i,j] = fp16(S * inv[i]*edge[i,j]*inv[j]); asum[i] = (1/S) * rowsum(fp16 values)
__global__ void norm_edge_rowsum(const float* __restrict__ edge, const float* __restrict__ inv,
                                 __half* __restrict__ outh, float* __restrict__ asum) {
    const int row = blockIdx.x;
    const float s = inv[row] * SCALE_S;
    const float4* p  = reinterpret_cast<const float4*>(edge + (size_t)row * N_NODES);
    const float4* iv = reinterpret_cast<const float4*>(inv);
    __half2* q = reinterpret_cast<__half2*>(outh + (size_t)row * N_NODES);
    float acc = 0.f;
    for (int j = threadIdx.x; j < N_NODES / 4; j += blockDim.x) {
        float4 v = p[j];
        float4 w = iv[j];
        __half2 h01 = __floats2half2_rn(s * v.x * w.x, s * v.y * w.y);
        __half2 h23 = __floats2half2_rn(s * v.z * w.z, s * v.w * w.w);
        q[j * 2]     = h01;
        q[j * 2 + 1] = h23;
        float2 f01 = __half22float2(h01), f23 = __half22float2(h23);
        acc += (f01.x + f01.y) + (f23.x + f23.y);
    }
    #pragma unroll
    for (int o = 16; o > 0; o >>= 1) acc += __shfl_down_sync(0xffffffffu, acc, o);
    __shared__ float red[8];
    const int lane = threadIdx.x & 31, w = threadIdx.x >> 5;
    if (lane == 0) red[w] = acc;
    __syncthreads();
    if (w == 0) {
        acc = (lane < 8) ? red[lane] : 0.f;
        #pragma unroll
        for (int o = 4; o > 0; o >>= 1) acc += __shfl_down_sync(0xffffffffu, acc, o);
        if (lane == 0) asum[row] = acc * INV_S;
    }
}

// generic fp32 -> fp16 (4 per thread)
__global__ void conv_h(const float* __restrict__ in, __half* __restrict__ out) {
    const size_t i = ((size_t)blockIdx.x * blockDim.x + threadIdx.x) * 4;
    float4 v = *reinterpret_cast<const float4*>(in + i);
    __half2* q = reinterpret_cast<__half2*>(out + i);
    q[0] = __floats2half2_rn(v.x, v.y);
    q[1] = __floats2half2_rn(v.z, v.w);
}

// Gh = fp16(G * INV_S)   (GEMM_a output is scaled by S)
__global__ void epi_scale_h(const float* __restrict__ in, __half* __restrict__ out) {
    const size_t i = ((size_t)blockIdx.x * blockDim.x + threadIdx.x) * 4;
    float4 v = *reinterpret_cast<const float4*>(in + i);
    __half2* q = reinterpret_cast<__half2*>(out + i);
    q[0] = __floats2half2_rn(v.x * INV_S, v.y * INV_S);
    q[1] = __floats2half2_rn(v.z * INV_S, v.w * INV_S);
}

// XTh[c, n] = fp16(X[n, c]); X is [N_NODES, IN_C]
__global__ void transpose_x_h(const float* __restrict__ X, __half* __restrict__ XT) {
    __shared__ float t[32][33];
    const int bx = blockIdx.x * 32, by = blockIdx.y * 32;
    const int x = threadIdx.x, y = threadIdx.y;   // 32 x 8
    #pragma unroll
    for (int yy = y; yy < 32; yy += 8)
        t[yy][x] = X[(size_t)(by + yy) * IN_C + bx + x];
    __syncthreads();
    #pragma unroll
    for (int yy = y; yy < 32; yy += 8)
        XT[(size_t)(bx + yy) * N_NODES + by + x] = __float2half_rn(t[x][yy]);
}

// outT[n, m] = fp16(D0[m,n] + D1[m,n]); D is [M, Ncols]
__global__ void epi_transpose_sum2_h(const float* __restrict__ D0, const float* __restrict__ D1,
                                     __half* __restrict__ outT, int M, int Ncols) {
    __shared__ float t[32][33];
    const int bx = blockIdx.x * 32, by = blockIdx.y * 32;
    const int x = threadIdx.x, y = threadIdx.y;   // 32 x 8
    #pragma unroll
    for (int yy = y; yy < 32; yy += 8) {
        const size_t idx = (size_t)(by + yy) * Ncols + bx + x;
        t[yy][x] = D0[idx] + D1[idx];
    }
    __syncthreads();
    #pragma unroll
    for (int yy = y; yy < 32; yy += 8)
        outT[(size_t)(bx + yy) * M + by + x] = __float2half_rn(t[x][yy]);
}

// Hh[m,j] = fp16(relu(C[m,j] + asum[m]*b1[j]))
__global__ void epi_relu_biasrow_h(const float* __restrict__ C, const float* __restrict__ asum,
                                   const float* __restrict__ bias, __half* __restrict__ out,
                                   int Ncols) {
    const size_t i = (size_t)blockIdx.x * blockDim.x + threadIdx.x;    // float4 idx
    const int m  = (int)(i / (Ncols / 4));
    const int j4 = (int)(i % (Ncols / 4)) * 4;
    const float a = __ldg(asum + m);
    float4 c = *reinterpret_cast<const float4*>(C + (size_t)m * Ncols + j4);
    float4 b = *reinterpret_cast<const float4*>(bias + j4);
    __half2* q = reinterpret_cast<__half2*>(out + (size_t)m * Ncols + j4);
    q[0] = __floats2half2_rn(fmaxf(c.x + a * b.x, 0.f), fmaxf(c.y + a * b.y, 0.f));
    q[1] = __floats2half2_rn(fmaxf(c.z + a * b.z, 0.f), fmaxf(c.w + a * b.w, 0.f));
}

// out[m,j] = relu((C0+C1)*INV_S + asum[m]*b2[j])  (final, fp32)
__global__ void epi_relu_biasrow_sum2(const float* __restrict__ C0, const float* __restrict__ C1,
                                      const float* __restrict__ asum, const float* __restrict__ bias,
                                      float* __restrict__ out, int Ncols) {
    const size_t i = (size_t)blockIdx.x * blockDim.x + threadIdx.x;
    const int m  = (int)(i / (Ncols / 4));
    const int j4 = (int)(i % (Ncols / 4)) * 4;
    const float a = __ldg(asum + m);
    const size_t off = (size_t)m * Ncols + j4;
    float4 c0 = *reinterpret_cast<const float4*>(C0 + off);
    float4 c1 = *reinterpret_cast<const float4*>(C1 + off);
    float4 b  = *reinterpret_cast<const float4*>(bias + j4);
    float4 o = make_float4(fmaxf((c0.x + c1.x) * INV_S + a * b.x, 0.f),
                           fmaxf((c0.y + c1.y) * INV_S + a * b.y, 0.f),
                           fmaxf((c0.z + c1.z) * INV_S + a * b.z, 0.f),
                           fmaxf((c0.w + c1.w) * INV_S + a * b.w, 0.f));
    *reinterpret_cast<float4*>(out + off) = o;
}

// ---------------- launch ----------------
extern "C" void kernel_launch(void* const* d_in, const int* in_sizes, int n_in,
                              void* d_out, int out_size) {
    const float* point = (const float*)d_in[0];
    const float* edge  = (const float*)d_in[1];
    const float* W1    = (const float*)d_in[2];
    const float* b1    = (const float*)d_in[3];
    const float* W2    = (const float*)d_in[4];
    const float* b2    = (const float*)d_in[5];
    float* out = (float*)d_out;

    float *inv, *asum, *G, *C;
    __half *Ah, *XTh, *W1h, *W2h, *Gh, *Hh, *OsTh;
    cudaGetSymbolAddress((void**)&inv,  g_inv);
    cudaGetSymbolAddress((void**)&asum, g_asum);
    cudaGetSymbolAddress((void**)&Ah,   g_Ah);
    cudaGetSymbolAddress((void**)&XTh,  g_XTh);
    cudaGetSymbolAddress((void**)&W1h,  g_W1h);
    cudaGetSymbolAddress((void**)&W2h,  g_W2h);
    cudaGetSymbolAddress((void**)&Gh,   g_Gh);
    cudaGetSymbolAddress((void**)&Hh,   g_Hh);
    cudaGetSymbolAddress((void**)&OsTh, g_OsTh);
    cudaGetSymbolAddress((void**)&G,    g_G);
    cudaGetSymbolAddress((void**)&C,    g_C);

    cudaFuncSetAttribute(tc_gemm, cudaFuncAttributeMaxDynamicSharedMemorySize, SMEM_GEMM);

    const size_t SPLIT = (size_t)N_NODES * OUT_C;   // split-K partial buffer stride

    // #1..#3: normalization + X transpose (tc_gemm_a stays launch #4 for ncu)
    rowsum_rsqrt<<<N_NODES, 256>>>(edge, inv);
    norm_edge_rowsum<<<N_NODES, 256>>>(edge, inv, Ah, asum);
    transpose_x_h<<<dim3(IN_C / 32, N_NODES / 32), dim3(32, 8)>>>(point, XTh);

    // #4 GEMM_a: G = (S*Â) @ X  [8192, 512]  fp32 out (256 CTAs, 1 wave @2/SM)
    tc_gemm<<<dim3(IN_C / BN, N_NODES / BM, 1), NTHR, SMEM_GEMM>>>(
        Ah, XTh, G, N_NODES, N_NODES, N_NODES, IN_C, 0);

    // weight rounding (independent; after GEMM_a to keep launch order)
    conv_h<<<(HID_C * IN_C / 4) / 256, 256>>>(W1, W1h);
    conv_h<<<(OUT_C * HID_C / 4) / 256, 256>>>(W2, W2h);
    epi_scale_h<<<(N_NODES * IN_C / 4) / 256, 256>>>(G, Gh);   // Gh = fp16(G/S)

    // GEMM_b: C = G @ W1^T  [8192, 1024]  (512 CTAs, 2 waves)
    tc_gemm<<<dim3(HID_C / BN, N_NODES / BM, 1), NTHR, SMEM_GEMM>>>(
        Gh, W1h, C, IN_C, IN_C, IN_C, HID_C, 0);
    epi_relu_biasrow_h<<<(N_NODES * HID_C / 4) / 256, 256>>>(C, asum, b1, Hh, HID_C);

    // GEMM_c: split-K=2 -> D0,D1 in g_G  [8192, 256] each  (256 CTAs, 1 wave)
    tc_gemm<<<dim3(OUT_C / BN, N_NODES / BM, 2), NTHR, SMEM_GEMM>>>(
        Hh, W2h, G, HID_C, HID_C, HID_C / 2, OUT_C, SPLIT);
    epi_transpose_sum2_h<<<dim3(OUT_C / 32, N_NODES / 32), dim3(32, 8)>>>(
        G, G + SPLIT, OsTh, N_NODES, OUT_C);

    // GEMM_d: split-K=2 -> C0,C1 in g_C  [8192, 256] each  (256 CTAs, 1 wave)
    tc_gemm<<<dim3(OUT_C / BN, N_NODES / BM, 2), NTHR, SMEM_GEMM>>>(
        Ah, OsTh, C, N_NODES, N_NODES, N_NODES / 2, OUT_C, SPLIT);
    epi_relu_biasrow_sum2<<<(N_NODES * OUT_C / 4) / 256, 256>>>(C, C + SPLIT, asum, b2, out, OUT_C);
}

// round 13
// speedup vs baseline: 3.5961x; 1.0048x over previous
#include <cuda_runtime.h>
#include <cuda_fp16.h>
#include <mma.h>
#include <cstdint>
#include <cstddef>

using namespace nvcuda;

#define N_NODES 8192
#define IN_C    512
#define HID_C   1024
#define OUT_C   256

#define SCALE_S 4096.0f
#define INV_S   (1.0f / 4096.0f)

// ---------------- scratch (static device arrays; no allocations) ----------------
__device__ float  g_inv [N_NODES];
__device__ float  g_asum[N_NODES];                       // rowsum of Â (unscaled)
__device__ __half g_Ah  [(size_t)N_NODES * N_NODES];     // fp16(S * Â)  (128 MB)
__device__ __half g_XTh [(size_t)IN_C * N_NODES];        // fp16(X^T)
__device__ __half g_W1h [(size_t)HID_C * IN_C];
__device__ __half g_W2h [(size_t)OUT_C * HID_C];
__device__ __half g_Gh  [(size_t)N_NODES * IN_C];        // fp16(Â@X)   (GEMM_a fused out)
__device__ __half g_Hh  [(size_t)N_NODES * HID_C];       // fp16(hidden) (GEMM_b fused out)
__device__ __half g_OsTh[(size_t)OUT_C * N_NODES];       // fp16((H@W2^T)^T)
__device__ float  g_G   [(size_t)2 * N_NODES * OUT_C];   // GEMM_c split-K partials
__device__ float  g_C   [(size_t)2 * N_NODES * OUT_C];   // GEMM_d split-K partials

__device__ __forceinline__ uint32_t smem_u32(const void* p) {
    uint32_t a;
    asm("{ .reg .u64 t; cvta.to.shared.u64 t, %1; cvt.u32.u64 %0, t; }" : "=r"(a) : "l"(p));
    return a;
}
__device__ __forceinline__ void cp16(uint32_t dst, const void* src) {
    asm volatile("cp.async.cg.shared.global [%0], [%1], 16;" :: "r"(dst), "l"(src));
}
#define CP_COMMIT() asm volatile("cp.async.commit_group;" ::: "memory")
#define CP_WAIT1()  asm volatile("cp.async.wait_group 1;" ::: "memory")

// ---- fp16 wmma GEMM: 128x128 block, 256 thr, 8 warps of 32x64, 3-stage cp.async,
// ---- 2 CTAs/SM. Fused epilogue modes:
//   MODE 0: fp32 store (split-K partials)                -> Cout = float*
//   MODE 1: fp16 store, acc * INV_S                      -> Cout = __half*
//   MODE 2: fp16 store, relu(acc + asum[m]*bias[j])      -> Cout = __half*
// C[M,Ncols] = A[M,Klen] @ B[Ncols,Klen]^T, fp16 K-major operands.
// blockIdx.z = split-K slice: koff = z*Klen, Cout += z*csplit (MODE 0 only).
constexpr int NTHR = 256;
constexpr int BM = 128, BN = 128, BK = 64;                // BK halves = 128 B/row
constexpr int BKP = 72;                                   // 144 B/row padded
constexpr int STAGES = 3;
constexpr int A_STAGE_B = BM * BKP * 2;                   // 18432
constexpr int STAGE_B   = (BM + BN) * BKP * 2;            // 36864
constexpr int SMEM_GEMM = STAGES * STAGE_B;               // 110592 (x2 CTAs = 221184/SM)
constexpr int WMI = 2, WNI = 4;                           // 32x64 warp tile
constexpr int EPI_LD = BN + 4;                            // fp32 scratch stride (132)

template <int MODE>
__global__ __launch_bounds__(NTHR, 2) void tc_gemm(
    const __half* __restrict__ A, const __half* __restrict__ B,
    void* __restrict__ Cout, int strideA, int strideB,
    int Klen, int Ncols, size_t csplit,
    const float* __restrict__ asum, const float* __restrict__ bias)
{
    extern __shared__ __align__(16) char smem[];
    __half* sh = reinterpret_cast<__half*>(smem);
    const uint32_t sb = smem_u32(smem);

    const int tid  = threadIdx.x;
    const int warp = tid >> 5;
    const int bm0  = blockIdx.y * BM;
    const int bn0  = blockIdx.x * BN;
    const int koff = blockIdx.z * Klen;
    const int wm0 = (warp >> 1) * 32;    // 4 warp rows
    const int wn0 = (warp & 1) * 64;     // 2 warp cols
    const int NKB = Klen / BK;

    wmma::fragment<wmma::accumulator, 16, 16, 16, float> acc[WMI][WNI];
    #pragma unroll
    for (int i = 0; i < WMI; i++)
        #pragma unroll
        for (int j = 0; j < WNI; j++)
            wmma::fill_fragment(acc[i][j], 0.f);

    const __half* Abase = A + (size_t)bm0 * strideA + koff;
    const __half* Bbase = B + (size_t)bn0 * strideB + koff;

    const int lr = tid >> 3;             // 0..31 (32 rows per pass)
    const int lc = tid & 7;              // 16B chunk (8 halves) within 128B row

    auto load_stage = [&](int s, int kb) {
        const uint32_t abase = sb + s * STAGE_B;
        const uint32_t bbase = abase + A_STAGE_B;
        const __half* Ag = Abase + (size_t)kb * BK;
        const __half* Bg = Bbase + (size_t)kb * BK;
        #pragma unroll
        for (int i = 0; i < 4; i++) {    // A: 128 rows
            const int row = lr + i * 32;
            cp16(abase + row * (BKP * 2) + lc * 16, Ag + (size_t)row * strideA + lc * 8);
        }
        #pragma unroll
        for (int i = 0; i < 4; i++) {    // B: 128 rows
            const int row = lr + i * 32;
            cp16(bbase + row * (BKP * 2) + lc * 16, Bg + (size_t)row * strideB + lc * 8);
        }
    };

    #pragma unroll
    for (int p = 0; p < STAGES - 1; p++) { load_stage(p, p); CP_COMMIT(); }

    for (int kb = 0; kb < NKB; kb++) {
        CP_WAIT1();                  // stage kb resident
        __syncthreads();             // all warps done computing iter kb-1
        const int jn = kb + (STAGES - 1);
        if (jn < NKB) load_stage(jn % STAGES, jn);
        CP_COMMIT();                 // uniform group numbering (empty at tail)

        const int s = kb % STAGES;
        __half* As = sh + (size_t)s * (STAGE_B / 2);
        __half* Bs = As + (A_STAGE_B / 2);

        #pragma unroll
        for (int ks = 0; ks < BK / 16; ++ks) {
            wmma::fragment<wmma::matrix_a, 16, 16, 16, __half, wmma::row_major> af[WMI];
            wmma::fragment<wmma::matrix_b, 16, 16, 16, __half, wmma::col_major> bf[WNI];
            #pragma unroll
            for (int i = 0; i < WMI; i++)
                wmma::load_matrix_sync(af[i], As + (size_t)(wm0 + i * 16) * BKP + ks * 16, BKP);
            #pragma unroll
            for (int j = 0; j < WNI; j++)
                wmma::load_matrix_sync(bf[j], Bs + (size_t)(wn0 + j * 16) * BKP + ks * 16, BKP);
            #pragma unroll
            for (int i = 0; i < WMI; i++)
                #pragma unroll
                for (int j = 0; j < WNI; j++)
                    wmma::mma_sync(acc[i][j], af[i], bf[j], acc[i][j]);
        }
    }

    if (MODE == 0) {
        float* C = reinterpret_cast<float*>(Cout) + (size_t)blockIdx.z * csplit;
        #pragma unroll
        for (int i = 0; i < WMI; i++)
            #pragma unroll
            for (int j = 0; j < WNI; j++)
                wmma::store_matrix_sync(
                    &C[(size_t)(bm0 + wm0 + i * 16) * Ncols + (bn0 + wn0 + j * 16)],
                    acc[i][j], Ncols, wmma::mem_row_major);
    } else {
        // fused fp16 epilogue via SMEM scratch (stages no longer needed)
        __syncthreads();
        float* scr = reinterpret_cast<float*>(smem);      // [BM][EPI_LD]
        #pragma unroll
        for (int i = 0; i < WMI; i++)
            #pragma unroll
            for (int j = 0; j < WNI; j++)
                wmma::store_matrix_sync(
                    scr + (size_t)(wm0 + i * 16) * EPI_LD + (wn0 + j * 16),
                    acc[i][j], EPI_LD, wmma::mem_row_major);
        __syncthreads();
        __half* C = reinterpret_cast<__half*>(Cout);
        for (int idx = tid; idx < BM * (BN / 4); idx += NTHR) {
            const int row = idx >> 5;            // BN/4 = 32
            const int c4  = (idx & 31) * 4;
            float4 v = *reinterpret_cast<float4*>(scr + (size_t)row * EPI_LD + c4);
            float4 o;
            if (MODE == 1) {
                o = make_float4(v.x * INV_S, v.y * INV_S, v.z * INV_S, v.w * INV_S);
            } else {
                const float a = __ldg(asum + bm0 + row);
                float4 b = *reinterpret_cast<const float4*>(bias + bn0 + c4);
                o = make_float4(fmaxf(v.x + a * b.x, 0.f), fmaxf(v.y + a * b.y, 0.f),
                                fmaxf(v.z + a * b.z, 0.f), fmaxf(v.w + a * b.w, 0.f));
            }
            __half2* q = reinterpret_cast<__half2*>(C + (size_t)(bm0 + row) * Ncols + bn0 + c4);
            q[0] = __floats2half2_rn(o.x, o.y);
            q[1] = __floats2half2_rn(o.z, o.w);
        }
    }
}

// ---------------- pre/post kernels ----------------
__global__ void rowsum_rsqrt(const float* __restrict__ mat, float* __restrict__ out) {
    const int row = blockIdx.x;
    const float4* p = reinterpret_cast<const float4*>(mat + (size_t)row * N_NODES);
    float s = 0.f;
    for (int j = threadIdx.x; j < N_NODES / 4; j += blockDim.x) {
        float4 v = p[j]; s += (v.x + v.y) + (v.z + v.w);
    }
    #pragma unroll
    for (int o = 16; o > 0; o >>= 1) s += __shfl_down_sync(0xffffffffu, s, o);
    __shared__ float red[8];
    const int lane = threadIdx.x & 31, w = threadIdx.x >> 5;
    if (lane == 0) red[w] = s;
    __syncthreads();
    if (w == 0) {
        s = (lane < 8) ? red[lane] : 0.f;
        #pragma unroll
        for (int o = 4; o > 0; o >>= 1) s += __shfl_down_sync(0xffffffffu, s, o);
        if (lane == 0) out[row] = (s > 0.f) ? rsqrtf(s) : 0.f;
    }
}

// Ah[i,j] = fp16(S * inv[i]*edge[i,j]*inv[j]); asum[i] = (1/S) * rowsum(fp16 values)
__global__ void norm_edge_rowsum(const float* __restrict__ edge, const float* __restrict__ inv,
                                 __half* __restrict__ outh, float* __restrict__ asum) {
    const int row = blockIdx.x;
    const float s = inv[row] * SCALE_S;
    const float4* p  = reinterpret_cast<const float4*>(edge + (size_t)row * N_NODES);
    const float4* iv = reinterpret_cast<const float4*>(inv);
    __half2* q = reinterpret_cast<__half2*>(outh + (size_t)row * N_NODES);
    float acc = 0.f;
    for (int j = threadIdx.x; j < N_NODES / 4; j += blockDim.x) {
        float4 v = p[j];
        float4 w = iv[j];
        __half2 h01 = __floats2half2_rn(s * v.x * w.x, s * v.y * w.y);
        __half2 h23 = __floats2half2_rn(s * v.z * w.z, s * v.w * w.w);
        q[j * 2]     = h01;
        q[j * 2 + 1] = h23;
        float2 f01 = __half22float2(h01), f23 = __half22float2(h23);
        acc += (f01.x + f01.y) + (f23.x + f23.y);
    }
    #pragma unroll
    for (int o = 16; o > 0; o >>= 1) acc += __shfl_down_sync(0xffffffffu, acc, o);
    __shared__ float red[8];
    const int lane = threadIdx.x & 31, w = threadIdx.x >> 5;
    if (lane == 0) red[w] = acc;
    __syncthreads();
    if (w == 0) {
        acc = (lane < 8) ? red[lane] : 0.f;
        #pragma unroll
        for (int o = 4; o > 0; o >>= 1) acc += __shfl_down_sync(0xffffffffu, acc, o);
        if (lane == 0) asum[row] = acc * INV_S;
    }
}

// generic fp32 -> fp16 (4 per thread)
__global__ void conv_h(const float* __restrict__ in, __half* __restrict__ out) {
    const size_t i = ((size_t)blockIdx.x * blockDim.x + threadIdx.x) * 4;
    float4 v = *reinterpret_cast<const float4*>(in + i);
    __half2* q = reinterpret_cast<__half2*>(out + i);
    q[0] = __floats2half2_rn(v.x, v.y);
    q[1] = __floats2half2_rn(v.z, v.w);
}

// XTh[c, n] = fp16(X[n, c]); X is [N_NODES, IN_C]
__global__ void transpose_x_h(const float* __restrict__ X, __half* __restrict__ XT) {
    __shared__ float t[32][33];
    const int bx = blockIdx.x * 32, by = blockIdx.y * 32;
    const int x = threadIdx.x, y = threadIdx.y;   // 32 x 8
    #pragma unroll
    for (int yy = y; yy < 32; yy += 8)
        t[yy][x] = X[(size_t)(by + yy) * IN_C + bx + x];
    __syncthreads();
    #pragma unroll
    for (int yy = y; yy < 32; yy += 8)
        XT[(size_t)(bx + yy) * N_NODES + by + x] = __float2half_rn(t[x][yy]);
}

// outT[n, m] = fp16(D0[m,n] + D1[m,n]); D is [M, Ncols]
__global__ void epi_transpose_sum2_h(const float* __restrict__ D0, const float* __restrict__ D1,
                                     __half* __restrict__ outT, int M, int Ncols) {
    __shared__ float t[32][33];
    const int bx = blockIdx.x * 32, by = blockIdx.y * 32;
    const int x = threadIdx.x, y = threadIdx.y;   // 32 x 8
    #pragma unroll
    for (int yy = y; yy < 32; yy += 8) {
        const size_t idx = (size_t)(by + yy) * Ncols + bx + x;
        t[yy][x] = D0[idx] + D1[idx];
    }
    __syncthreads();
    #pragma unroll
    for (int yy = y; yy < 32; yy += 8)
        outT[(size_t)(bx + yy) * M + by + x] = __float2half_rn(t[x][yy]);
}

// out[m,j] = relu((C0+C1)*INV_S + asum[m]*b2[j])  (final, fp32)
__global__ void epi_relu_biasrow_sum2(const float* __restrict__ C0, const float* __restrict__ C1,
                                      const float* __restrict__ asum, const float* __restrict__ bias,
                                      float* __restrict__ out, int Ncols) {
    const size_t i = (size_t)blockIdx.x * blockDim.x + threadIdx.x;
    const int m  = (int)(i / (Ncols / 4));
    const int j4 = (int)(i % (Ncols / 4)) * 4;
    const float a = __ldg(asum + m);
    const size_t off = (size_t)m * Ncols + j4;
    float4 c0 = *reinterpret_cast<const float4*>(C0 + off);
    float4 c1 = *reinterpret_cast<const float4*>(C1 + off);
    float4 b  = *reinterpret_cast<const float4*>(bias + j4);
    float4 o = make_float4(fmaxf((c0.x + c1.x) * INV_S + a * b.x, 0.f),
                           fmaxf((c0.y + c1.y) * INV_S + a * b.y, 0.f),
                           fmaxf((c0.z + c1.z) * INV_S + a * b.z, 0.f),
                           fmaxf((c0.w + c1.w) * INV_S + a * b.w, 0.f));
    *reinterpret_cast<float4*>(out + off) = o;
}

// ---------------- launch ----------------
extern "C" void kernel_launch(void* const* d_in, const int* in_sizes, int n_in,
                              void* d_out, int out_size) {
    const float* point = (const float*)d_in[0];
    const float* edge  = (const float*)d_in[1];
    const float* W1    = (const float*)d_in[2];
    const float* b1    = (const float*)d_in[3];
    const float* W2    = (const float*)d_in[4];
    const float* b2    = (const float*)d_in[5];
    float* out = (float*)d_out;

    float *inv, *asum, *G, *C;
    __half *Ah, *XTh, *W1h, *W2h, *Gh, *Hh, *OsTh;
    cudaGetSymbolAddress((void**)&inv,  g_inv);
    cudaGetSymbolAddress((void**)&asum, g_asum);
    cudaGetSymbolAddress((void**)&Ah,   g_Ah);
    cudaGetSymbolAddress((void**)&XTh,  g_XTh);
    cudaGetSymbolAddress((void**)&W1h,  g_W1h);
    cudaGetSymbolAddress((void**)&W2h,  g_W2h);
    cudaGetSymbolAddress((void**)&Gh,   g_Gh);
    cudaGetSymbolAddress((void**)&Hh,   g_Hh);
    cudaGetSymbolAddress((void**)&OsTh, g_OsTh);
    cudaGetSymbolAddress((void**)&G,    g_G);
    cudaGetSymbolAddress((void**)&C,    g_C);

    cudaFuncSetAttribute(tc_gemm<0>, cudaFuncAttributeMaxDynamicSharedMemorySize, SMEM_GEMM);
    cudaFuncSetAttribute(tc_gemm<1>, cudaFuncAttributeMaxDynamicSharedMemorySize, SMEM_GEMM);
    cudaFuncSetAttribute(tc_gemm<2>, cudaFuncAttributeMaxDynamicSharedMemorySize, SMEM_GEMM);

    const size_t SPLIT = (size_t)N_NODES * OUT_C;   // split-K partial buffer stride

    // #1..#3: normalization + X transpose (GEMM_a stays launch #4 for ncu)
    rowsum_rsqrt<<<N_NODES, 256>>>(edge, inv);
    norm_edge_rowsum<<<N_NODES, 256>>>(edge, inv, Ah, asum);
    transpose_x_h<<<dim3(IN_C / 32, N_NODES / 32), dim3(32, 8)>>>(point, XTh);

    // #4 GEMM_a (MODE 1): Gh = fp16((S*Â)@X * 1/S)  [8192,512]  (256 CTAs, 1 wave)
    tc_gemm<1><<<dim3(IN_C / BN, N_NODES / BM, 1), NTHR, SMEM_GEMM>>>(
        Ah, XTh, Gh, N_NODES, N_NODES, N_NODES, IN_C, 0, nullptr, nullptr);

    // weight conversion (independent; after GEMM_a to keep launch order)
    conv_h<<<(HID_C * IN_C / 4) / 256, 256>>>(W1, W1h);
    conv_h<<<(OUT_C * HID_C / 4) / 256, 256>>>(W2, W2h);

    // GEMM_b (MODE 2): Hh = fp16(relu(G@W1^T + asum*b1))  [8192,1024]  (512 CTAs)
    tc_gemm<2><<<dim3(HID_C / BN, N_NODES / BM, 1), NTHR, SMEM_GEMM>>>(
        Gh, W1h, Hh, IN_C, IN_C, IN_C, HID_C, 0, asum, b1);

    // GEMM_c (MODE 0, split-K=2): D0,D1 = H@W2^T partials  [8192,256]  (256 CTAs)
    tc_gemm<0><<<dim3(OUT_C / BN, N_NODES / BM, 2), NTHR, SMEM_GEMM>>>(
        Hh, W2h, G, HID_C, HID_C, HID_C / 2, OUT_C, SPLIT, nullptr, nullptr);
    epi_transpose_sum2_h<<<dim3(OUT_C / 32, N_NODES / 32), dim3(32, 8)>>>(
        G, G + SPLIT, OsTh, N_NODES, OUT_C);

    // GEMM_d (MODE 0, split-K=2): C0,C1 = (S*Â)@Os partials  [8192,256]  (256 CTAs)
    tc_gemm<0><<<dim3(OUT_C / BN, N_NODES / BM, 2), NTHR, SMEM_GEMM>>>(
        Ah, OsTh, C, N_NODES, N_NODES, N_NODES / 2, OUT_C, SPLIT, nullptr, nullptr);
    epi_relu_biasrow_sum2<<<(N_NODES * OUT_C / 4) / 256, 256>>>(C, C + SPLIT, asum, b2, out, OUT_C);
}

// round 14
// speedup vs baseline: 3.6458x; 1.0138x over previous
#include <cuda_runtime.h>
#include <cuda_fp16.h>
#include <mma.h>
#include <cstdint>
#include <cstddef>

using namespace nvcuda;

#define N_NODES 8192
#define IN_C    512
#define HID_C   1024
#define OUT_C   256

// ---------------- scratch (static device arrays; no allocations) ----------------
__device__ float  g_inv [N_NODES];                       // D^{-1/2}
__device__ float  g_asum[N_NODES];                       // rowsum of effective Â
__device__ __half g_Ah  [(size_t)N_NODES * N_NODES];     // fp16(edge), RAW (128 MB)
__device__ __half g_XTh [(size_t)IN_C * N_NODES];        // fp16(inv_n * X^T)
__device__ __half g_W1h [(size_t)HID_C * IN_C];
__device__ __half g_W2h [(size_t)OUT_C * HID_C];
__device__ __half g_Gh  [(size_t)N_NODES * IN_C];        // fp16(Â@X)   (GEMM_a fused out)
__device__ __half g_Hh  [(size_t)N_NODES * HID_C];       // fp16(hidden) (GEMM_b fused out)
__device__ __half g_OsTh[(size_t)OUT_C * N_NODES];       // fp16(inv_m * Os^T)
__device__ float  g_G   [(size_t)2 * N_NODES * OUT_C];   // GEMM_c split-K partials
__device__ float  g_C   [(size_t)2 * N_NODES * OUT_C];   // GEMM_d split-K partials

__device__ __forceinline__ uint32_t smem_u32(const void* p) {
    uint32_t a;
    asm("{ .reg .u64 t; cvta.to.shared.u64 t, %1; cvt.u32.u64 %0, t; }" : "=r"(a) : "l"(p));
    return a;
}
__device__ __forceinline__ void cp16(uint32_t dst, const void* src) {
    asm volatile("cp.async.cg.shared.global [%0], [%1], 16;" :: "r"(dst), "l"(src));
}
#define CP_COMMIT() asm volatile("cp.async.commit_group;" ::: "memory")
#define CP_WAIT1()  asm volatile("cp.async.wait_group 1;" ::: "memory")

// ---- fp16 wmma GEMM: 128x128 block, 256 thr, 8 warps of 32x64, 3-stage cp.async,
// ---- 2 CTAs/SM. Fused epilogue modes:
//   MODE 0: fp32 store (split-K partials)                      -> Cout = float*
//   MODE 1: fp16 store, acc * rowvec[m]                        -> Cout = __half*
//   MODE 2: fp16 store, relu(acc + rowvec[m]*bias[j])          -> Cout = __half*
// C[M,Ncols] = A[M,Klen] @ B[Ncols,Klen]^T, fp16 K-major operands.
// blockIdx.z = split-K slice: koff = z*Klen, Cout += z*csplit (MODE 0 only).
constexpr int NTHR = 256;
constexpr int BM = 128, BN = 128, BK = 64;                // BK halves = 128 B/row
constexpr int BKP = 72;                                   // 144 B/row padded
constexpr int STAGES = 3;
constexpr int A_STAGE_B = BM * BKP * 2;                   // 18432
constexpr int STAGE_B   = (BM + BN) * BKP * 2;            // 36864
constexpr int SMEM_GEMM = STAGES * STAGE_B;               // 110592 (x2 CTAs = 221184/SM)
constexpr int WMI = 2, WNI = 4;                           // 32x64 warp tile
constexpr int EPI_LD = BN + 4;                            // fp32 scratch stride (132)

template <int MODE>
__global__ __launch_bounds__(NTHR, 2) void tc_gemm(
    const __half* __restrict__ A, const __half* __restrict__ B,
    void* __restrict__ Cout, int strideA, int strideB,
    int Klen, int Ncols, size_t csplit,
    const float* __restrict__ rowvec, const float* __restrict__ bias)
{
    extern __shared__ __align__(16) char smem[];
    __half* sh = reinterpret_cast<__half*>(smem);
    const uint32_t sb = smem_u32(smem);

    const int tid  = threadIdx.x;
    const int warp = tid >> 5;
    const int bm0  = blockIdx.y * BM;
    const int bn0  = blockIdx.x * BN;
    const int koff = blockIdx.z * Klen;
    const int wm0 = (warp >> 1) * 32;    // 4 warp rows
    const int wn0 = (warp & 1) * 64;     // 2 warp cols
    const int NKB = Klen / BK;

    wmma::fragment<wmma::accumulator, 16, 16, 16, float> acc[WMI][WNI];
    #pragma unroll
    for (int i = 0; i < WMI; i++)
        #pragma unroll
        for (int j = 0; j < WNI; j++)
            wmma::fill_fragment(acc[i][j], 0.f);

    const __half* Abase = A + (size_t)bm0 * strideA + koff;
    const __half* Bbase = B + (size_t)bn0 * strideB + koff;

    const int lr = tid >> 3;             // 0..31 (32 rows per pass)
    const int lc = tid & 7;              // 16B chunk (8 halves) within 128B row

    auto load_stage = [&](int s, int kb) {
        const uint32_t abase = sb + s * STAGE_B;
        const uint32_t bbase = abase + A_STAGE_B;
        const __half* Ag = Abase + (size_t)kb * BK;
        const __half* Bg = Bbase + (size_t)kb * BK;
        #pragma unroll
        for (int i = 0; i < 4; i++) {    // A: 128 rows
            const int row = lr + i * 32;
            cp16(abase + row * (BKP * 2) + lc * 16, Ag + (size_t)row * strideA + lc * 8);
        }
        #pragma unroll
        for (int i = 0; i < 4; i++) {    // B: 128 rows
            const int row = lr + i * 32;
            cp16(bbase + row * (BKP * 2) + lc * 16, Bg + (size_t)row * strideB + lc * 8);
        }
    };

    #pragma unroll
    for (int p = 0; p < STAGES - 1; p++) { load_stage(p, p); CP_COMMIT(); }

    for (int kb = 0; kb < NKB; kb++) {
        CP_WAIT1();                  // stage kb resident
        __syncthreads();             // all warps done computing iter kb-1
        const int jn = kb + (STAGES - 1);
        if (jn < NKB) load_stage(jn % STAGES, jn);
        CP_COMMIT();                 // uniform group numbering (empty at tail)

        const int s = kb % STAGES;
        __half* As = sh + (size_t)s * (STAGE_B / 2);
        __half* Bs = As + (A_STAGE_B / 2);

        #pragma unroll
        for (int ks = 0; ks < BK / 16; ++ks) {
            wmma::fragment<wmma::matrix_a, 16, 16, 16, __half, wmma::row_major> af[WMI];
            wmma::fragment<wmma::matrix_b, 16, 16, 16, __half, wmma::col_major> bf[WNI];
            #pragma unroll
            for (int i = 0; i < WMI; i++)
                wmma::load_matrix_sync(af[i], As + (size_t)(wm0 + i * 16) * BKP + ks * 16, BKP);
            #pragma unroll
            for (int j = 0; j < WNI; j++)
                wmma::load_matrix_sync(bf[j], Bs + (size_t)(wn0 + j * 16) * BKP + ks * 16, BKP);
            #pragma unroll
            for (int i = 0; i < WMI; i++)
                #pragma unroll
                for (int j = 0; j < WNI; j++)
                    wmma::mma_sync(acc[i][j], af[i], bf[j], acc[i][j]);
        }
    }

    if (MODE == 0) {
        float* C = reinterpret_cast<float*>(Cout) + (size_t)blockIdx.z * csplit;
        #pragma unroll
        for (int i = 0; i < WMI; i++)
            #pragma unroll
            for (int j = 0; j < WNI; j++)
                wmma::store_matrix_sync(
                    &C[(size_t)(bm0 + wm0 + i * 16) * Ncols + (bn0 + wn0 + j * 16)],
                    acc[i][j], Ncols, wmma::mem_row_major);
    } else {
        // fused fp16 epilogue via SMEM scratch (stages no longer needed)
        __syncthreads();
        float* scr = reinterpret_cast<float*>(smem);      // [BM][EPI_LD]
        #pragma unroll
        for (int i = 0; i < WMI; i++)
            #pragma unroll
            for (int j = 0; j < WNI; j++)
                wmma::store_matrix_sync(
                    scr + (size_t)(wm0 + i * 16) * EPI_LD + (wn0 + j * 16),
                    acc[i][j], EPI_LD, wmma::mem_row_major);
        __syncthreads();
        __half* C = reinterpret_cast<__half*>(Cout);
        for (int idx = tid; idx < BM * (BN / 4); idx += NTHR) {
            const int row = idx >> 5;            // BN/4 = 32
            const int c4  = (idx & 31) * 4;
            float4 v = *reinterpret_cast<float4*>(scr + (size_t)row * EPI_LD + c4);
            float4 o;
            const float a = __ldg(rowvec + bm0 + row);
            if (MODE == 1) {
                o = make_float4(v.x * a, v.y * a, v.z * a, v.w * a);
            } else {
                float4 b = *reinterpret_cast<const float4*>(bias + bn0 + c4);
                o = make_float4(fmaxf(v.x + a * b.x, 0.f), fmaxf(v.y + a * b.y, 0.f),
                                fmaxf(v.z + a * b.z, 0.f), fmaxf(v.w + a * b.w, 0.f));
            }
            __half2* q = reinterpret_cast<__half2*>(C + (size_t)(bm0 + row) * Ncols + bn0 + c4);
            q[0] = __floats2half2_rn(o.x, o.y);
            q[1] = __floats2half2_rn(o.z, o.w);
        }
    }
}

// ---------------- pre/post kernels ----------------
// Pass 1 (fused): Ah[i,j] = fp16(edge[i,j]); inv[i] = rsqrt(rowsum fp32)
__global__ void convert_rowsum_inv(const float* __restrict__ edge,
                                   __half* __restrict__ Ah, float* __restrict__ inv) {
    const int row = blockIdx.x;
    const float4* p = reinterpret_cast<const float4*>(edge + (size_t)row * N_NODES);
    __half2* q = reinterpret_cast<__half2*>(Ah + (size_t)row * N_NODES);
    float s = 0.f;
    for (int j = threadIdx.x; j < N_NODES / 4; j += blockDim.x) {
        float4 v = p[j];
        q[j * 2]     = __floats2half2_rn(v.x, v.y);
        q[j * 2 + 1] = __floats2half2_rn(v.z, v.w);
        s += (v.x + v.y) + (v.z + v.w);
    }
    #pragma unroll
    for (int o = 16; o > 0; o >>= 1) s += __shfl_down_sync(0xffffffffu, s, o);
    __shared__ float red[8];
    const int lane = threadIdx.x & 31, w = threadIdx.x >> 5;
    if (lane == 0) red[w] = s;
    __syncthreads();
    if (w == 0) {
        s = (lane < 8) ? red[lane] : 0.f;
        #pragma unroll
        for (int o = 4; o > 0; o >>= 1) s += __shfl_down_sync(0xffffffffu, s, o);
        if (lane == 0) inv[row] = (s > 0.f) ? rsqrtf(s) : 0.f;
    }
}

// asum[i] = inv[i] * sum_j Ah[i,j]*inv[j]   (rowsum of effective Â)
__global__ void asum_gemv(const __half* __restrict__ Ah, const float* __restrict__ inv,
                          float* __restrict__ asum) {
    const int row = blockIdx.x;
    const __half2* p = reinterpret_cast<const __half2*>(Ah + (size_t)row * N_NODES);
    const float4* iv = reinterpret_cast<const float4*>(inv);
    float s = 0.f;
    for (int j = threadIdx.x; j < N_NODES / 4; j += blockDim.x) {
        __half2 h01 = p[j * 2], h23 = p[j * 2 + 1];
        float2 f01 = __half22float2(h01), f23 = __half22float2(h23);
        float4 w = iv[j];
        s += f01.x * w.x + f01.y * w.y + f23.x * w.z + f23.y * w.w;
    }
    #pragma unroll
    for (int o = 16; o > 0; o >>= 1) s += __shfl_down_sync(0xffffffffu, s, o);
    __shared__ float red[8];
    const int lane = threadIdx.x & 31, w = threadIdx.x >> 5;
    if (lane == 0) red[w] = s;
    __syncthreads();
    if (w == 0) {
        s = (lane < 8) ? red[lane] : 0.f;
        #pragma unroll
        for (int o = 4; o > 0; o >>= 1) s += __shfl_down_sync(0xffffffffu, s, o);
        if (lane == 0) asum[row] = s * __ldg(inv + row);
    }
}

// generic fp32 -> fp16 (4 per thread)
__global__ void conv_h(const float* __restrict__ in, __half* __restrict__ out) {
    const size_t i = ((size_t)blockIdx.x * blockDim.x + threadIdx.x) * 4;
    float4 v = *reinterpret_cast<const float4*>(in + i);
    __half2* q = reinterpret_cast<__half2*>(out + i);
    q[0] = __floats2half2_rn(v.x, v.y);
    q[1] = __floats2half2_rn(v.z, v.w);
}

// XTh[c, n] = fp16(inv[n] * X[n, c]); X is [N_NODES, IN_C]
__global__ void transpose_x_h(const float* __restrict__ X, const float* __restrict__ inv,
                              __half* __restrict__ XT) {
    __shared__ float t[32][33];
    const int bx = blockIdx.x * 32, by = blockIdx.y * 32;
    const int x = threadIdx.x, y = threadIdx.y;   // 32 x 8
    #pragma unroll
    for (int yy = y; yy < 32; yy += 8)
        t[yy][x] = X[(size_t)(by + yy) * IN_C + bx + x] * __ldg(inv + by + yy);
    __syncthreads();
    #pragma unroll
    for (int yy = y; yy < 32; yy += 8)
        XT[(size_t)(bx + yy) * N_NODES + by + x] = __float2half_rn(t[x][yy]);
}

// outT[n, m] = fp16(inv[m] * (D0[m,n] + D1[m,n])); D is [M, Ncols]
__global__ void epi_transpose_sum2_h(const float* __restrict__ D0, const float* __restrict__ D1,
                                     const float* __restrict__ inv,
                                     __half* __restrict__ outT, int M, int Ncols) {
    __shared__ float t[32][33];
    const int bx = blockIdx.x * 32, by = blockIdx.y * 32;
    const int x = threadIdx.x, y = threadIdx.y;   // 32 x 8
    #pragma unroll
    for (int yy = y; yy < 32; yy += 8) {
        const size_t idx = (size_t)(by + yy) * Ncols + bx + x;
        t[yy][x] = (D0[idx] + D1[idx]) * __ldg(inv + by + yy);
    }
    __syncthreads();
    #pragma unroll
    for (int yy = y; yy < 32; yy += 8)
        outT[(size_t)(bx + yy) * M + by + x] = __float2half_rn(t[x][yy]);
}

// out[m,j] = relu(inv[m]*(C0+C1) + asum[m]*b2[j])  (final, fp32)
__global__ void epi_relu_biasrow_sum2(const float* __restrict__ C0, const float* __restrict__ C1,
                                      const float* __restrict__ inv, const float* __restrict__ asum,
                                      const float* __restrict__ bias,
                                      float* __restrict__ out, int Ncols) {
    const size_t i = (size_t)blockIdx.x * blockDim.x + threadIdx.x;
    const int m  = (int)(i / (Ncols / 4));
    const int j4 = (int)(i % (Ncols / 4)) * 4;
    const float a = __ldg(asum + m);
    const float s = __ldg(inv + m);
    const size_t off = (size_t)m * Ncols + j4;
    float4 c0 = *reinterpret_cast<const float4*>(C0 + off);
    float4 c1 = *reinterpret_cast<const float4*>(C1 + off);
    float4 b  = *reinterpret_cast<const float4*>(bias + j4);
    float4 o = make_float4(fmaxf((c0.x + c1.x) * s + a * b.x, 0.f),
                           fmaxf((c0.y + c1.y) * s + a * b.y, 0.f),
                           fmaxf((c0.z + c1.z) * s + a * b.z, 0.f),
                           fmaxf((c0.w + c1.w) * s + a * b.w, 0.f));
    *reinterpret_cast<float4*>(out + off) = o;
}

// ---------------- launch ----------------
extern "C" void kernel_launch(void* const* d_in, const int* in_sizes, int n_in,
                              void* d_out, int out_size) {
    const float* point = (const float*)d_in[0];
    const float* edge  = (const float*)d_in[1];
    const float* W1    = (const float*)d_in[2];
    const float* b1    = (const float*)d_in[3];
    const float* W2    = (const float*)d_in[4];
    const float* b2    = (const float*)d_in[5];
    float* out = (float*)d_out;

    float *inv, *asum, *G, *C;
    __half *Ah, *XTh, *W1h, *W2h, *Gh, *Hh, *OsTh;
    cudaGetSymbolAddress((void**)&inv,  g_inv);
    cudaGetSymbolAddress((void**)&asum, g_asum);
    cudaGetSymbolAddress((void**)&Ah,   g_Ah);
    cudaGetSymbolAddress((void**)&XTh,  g_XTh);
    cudaGetSymbolAddress((void**)&W1h,  g_W1h);
    cudaGetSymbolAddress((void**)&W2h,  g_W2h);
    cudaGetSymbolAddress((void**)&Gh,   g_Gh);
    cudaGetSymbolAddress((void**)&Hh,   g_Hh);
    cudaGetSymbolAddress((void**)&OsTh, g_OsTh);
    cudaGetSymbolAddress((void**)&G,    g_G);
    cudaGetSymbolAddress((void**)&C,    g_C);

    cudaFuncSetAttribute(tc_gemm<0>, cudaFuncAttributeMaxDynamicSharedMemorySize, SMEM_GEMM);
    cudaFuncSetAttribute(tc_gemm<1>, cudaFuncAttributeMaxDynamicSharedMemorySize, SMEM_GEMM);
    cudaFuncSetAttribute(tc_gemm<2>, cudaFuncAttributeMaxDynamicSharedMemorySize, SMEM_GEMM);

    const size_t SPLIT = (size_t)N_NODES * OUT_C;   // split-K partial buffer stride

    // #1: edge fp32 -> fp16 raw + rowsum + inv (fused single pass over edge)
    convert_rowsum_inv<<<N_NODES, 256>>>(edge, Ah, inv);
    // #2: asum = inv_i * (A_fp16 @ inv)
    asum_gemv<<<N_NODES, 256>>>(Ah, inv, asum);
    // #3: XTh = fp16(inv_n * X^T)
    transpose_x_h<<<dim3(IN_C / 32, N_NODES / 32), dim3(32, 8)>>>(point, inv, XTh);

    // #4 GEMM_a (MODE 1): Gh = fp16(inv_m * (A @ Xs))  [8192,512]  (256 CTAs, 1 wave)
    tc_gemm<1><<<dim3(IN_C / BN, N_NODES / BM, 1), NTHR, SMEM_GEMM>>>(
        Ah, XTh, Gh, N_NODES, N_NODES, N_NODES, IN_C, 0, inv, nullptr);

    // weight conversion (independent; after GEMM_a to keep launch order)
    conv_h<<<(HID_C * IN_C / 4) / 256, 256>>>(W1, W1h);
    conv_h<<<(OUT_C * HID_C / 4) / 256, 256>>>(W2, W2h);

    // GEMM_b (MODE 2): Hh = fp16(relu(G@W1^T + asum*b1))  [8192,1024]  (512 CTAs)
    tc_gemm<2><<<dim3(HID_C / BN, N_NODES / BM, 1), NTHR, SMEM_GEMM>>>(
        Gh, W1h, Hh, IN_C, IN_C, IN_C, HID_C, 0, asum, b1);

    // GEMM_c (MODE 0, split-K=2): D0,D1 = H@W2^T partials  [8192,256]  (256 CTAs)
    tc_gemm<0><<<dim3(OUT_C / BN, N_NODES / BM, 2), NTHR, SMEM_GEMM>>>(
        Hh, W2h, G, HID_C, HID_C, HID_C / 2, OUT_C, SPLIT, nullptr, nullptr);
    // OsTh = fp16(inv_m * (D0+D1)^T)
    epi_transpose_sum2_h<<<dim3(OUT_C / 32, N_NODES / 32), dim3(32, 8)>>>(
        G, G + SPLIT, inv, OsTh, N_NODES, OUT_C);

    // GEMM_d (MODE 0, split-K=2): C0,C1 = A@Os partials  [8192,256]  (256 CTAs)
    tc_gemm<0><<<dim3(OUT_C / BN, N_NODES / BM, 2), NTHR, SMEM_GEMM>>>(
        Ah, OsTh, C, N_NODES, N_NODES, N_NODES / 2, OUT_C, SPLIT, nullptr, nullptr);
    // out = relu(inv_m*(C0+C1) + asum*b2)
    epi_relu_biasrow_sum2<<<(N_NODES * OUT_C / 4) / 256, 256>>>(
        C, C + SPLIT, inv, asum, b2, out, OUT_C);
}

// round 15
// speedup vs baseline: 3.6923x; 1.0127x over previous
#include <cuda_runtime.h>
#include <cuda_fp16.h>
#include <mma.h>
#include <cstdint>
#include <cstddef>

using namespace nvcuda;

#define N_NODES 8192
#define IN_C    512
#define HID_C   1024
#define OUT_C   256

// ---------------- scratch (static device arrays; no allocations) ----------------
__device__ float  g_inv [N_NODES];                       // D^{-1/2}
__device__ float  g_asum[N_NODES];                       // rowsum of effective Â
__device__ __half g_Ah  [(size_t)N_NODES * N_NODES];     // fp16(edge), RAW (128 MB)
__device__ __half g_XTh [(size_t)IN_C * N_NODES];        // fp16(inv_n * X^T)
__device__ __half g_W1h [(size_t)HID_C * IN_C];
__device__ __half g_W2h [(size_t)OUT_C * HID_C];
__device__ __half g_Gh  [(size_t)N_NODES * IN_C];        // fp16(Â@X)   (GEMM_a fused out)
__device__ __half g_Hh  [(size_t)N_NODES * HID_C];       // fp16(hidden) (GEMM_b fused out)
__device__ __half g_OsTh[(size_t)OUT_C * N_NODES];       // fp16(inv_m * Os^T)
__device__ float  g_G   [(size_t)2 * N_NODES * OUT_C];   // GEMM_c split-K partials
__device__ float  g_C   [(size_t)2 * N_NODES * OUT_C];   // GEMM_d split-K partials

__device__ __forceinline__ uint32_t smem_u32(const void* p) {
    uint32_t a;
    asm("{ .reg .u64 t; cvta.to.shared.u64 t, %1; cvt.u32.u64 %0, t; }" : "=r"(a) : "l"(p));
    return a;
}
__device__ __forceinline__ void cp16(uint32_t dst, const void* src) {
    asm volatile("cp.async.cg.shared.global [%0], [%1], 16;" :: "r"(dst), "l"(src));
}
#define CP_COMMIT() asm volatile("cp.async.commit_group;" ::: "memory")
#define CP_WAIT1()  asm volatile("cp.async.wait_group 1;" ::: "memory")

// ---- fp16 wmma GEMM: 128x128 block, 256 thr, 8 warps of 32x64, 3-stage cp.async,
// ---- 2 CTAs/SM. Fused epilogue modes:
//   MODE 0: fp32 store (split-K partials)                      -> Cout = float*
//   MODE 1: fp16 store, acc * rowvec[m]                        -> Cout = __half*
//   MODE 2: fp16 store, relu(acc + rowvec[m]*bias[j])          -> Cout = __half*
// C[M,Ncols] = A[M,Klen] @ B[Ncols,Klen]^T, fp16 K-major operands.
// blockIdx.z = split-K slice: koff = z*Klen, Cout += z*csplit (MODE 0 only).
constexpr int NTHR = 256;
constexpr int BM = 128, BN = 128, BK = 64;                // BK halves = 128 B/row
constexpr int BKP = 72;                                   // 144 B/row padded
constexpr int STAGES = 3;
constexpr int A_STAGE_B = BM * BKP * 2;                   // 18432
constexpr int STAGE_B   = (BM + BN) * BKP * 2;            // 36864
constexpr int SMEM_GEMM = STAGES * STAGE_B;               // 110592 (x2 CTAs = 221184/SM)
constexpr int WMI = 2, WNI = 4;                           // 32x64 warp tile
constexpr int EPI_LD = BN + 4;                            // fp32 scratch stride (132)

template <int MODE>
__global__ __launch_bounds__(NTHR, 2) void tc_gemm(
    const __half* __restrict__ A, const __half* __restrict__ B,
    void* __restrict__ Cout, int strideA, int strideB,
    int Klen, int Ncols, size_t csplit,
    const float* __restrict__ rowvec, const float* __restrict__ bias)
{
    extern __shared__ __align__(16) char smem[];
    __half* sh = reinterpret_cast<__half*>(smem);
    const uint32_t sb = smem_u32(smem);

    const int tid  = threadIdx.x;
    const int warp = tid >> 5;
    const int bm0  = blockIdx.y * BM;
    const int bn0  = blockIdx.x * BN;
    const int koff = blockIdx.z * Klen;
    const int wm0 = (warp >> 1) * 32;    // 4 warp rows
    const int wn0 = (warp & 1) * 64;     // 2 warp cols
    const int NKB = Klen / BK;

    wmma::fragment<wmma::accumulator, 16, 16, 16, float> acc[WMI][WNI];
    #pragma unroll
    for (int i = 0; i < WMI; i++)
        #pragma unroll
        for (int j = 0; j < WNI; j++)
            wmma::fill_fragment(acc[i][j], 0.f);

    const __half* Abase = A + (size_t)bm0 * strideA + koff;
    const __half* Bbase = B + (size_t)bn0 * strideB + koff;

    const int lr = tid >> 3;             // 0..31 (32 rows per pass)
    const int lc = tid & 7;              // 16B chunk (8 halves) within 128B row

    auto load_stage = [&](int s, int kb) {
        const uint32_t abase = sb + s * STAGE_B;
        const uint32_t bbase = abase + A_STAGE_B;
        const __half* Ag = Abase + (size_t)kb * BK;
        const __half* Bg = Bbase + (size_t)kb * BK;
        #pragma unroll
        for (int i = 0; i < 4; i++) {    // A: 128 rows
            const int row = lr + i * 32;
            cp16(abase + row * (BKP * 2) + lc * 16, Ag + (size_t)row * strideA + lc * 8);
        }
        #pragma unroll
        for (int i = 0; i < 4; i++) {    // B: 128 rows
            const int row = lr + i * 32;
            cp16(bbase + row * (BKP * 2) + lc * 16, Bg + (size_t)row * strideB + lc * 8);
        }
    };

    #pragma unroll
    for (int p = 0; p < STAGES - 1; p++) { load_stage(p, p); CP_COMMIT(); }

    for (int kb = 0; kb < NKB; kb++) {
        CP_WAIT1();                  // stage kb resident
        __syncthreads();             // all warps done computing iter kb-1
        const int jn = kb + (STAGES - 1);
        if (jn < NKB) load_stage(jn % STAGES, jn);
        CP_COMMIT();                 // uniform group numbering (empty at tail)

        const int s = kb % STAGES;
        __half* As = sh + (size_t)s * (STAGE_B / 2);
        __half* Bs = As + (A_STAGE_B / 2);

        #pragma unroll
        for (int ks = 0; ks < BK / 16; ++ks) {
            wmma::fragment<wmma::matrix_a, 16, 16, 16, __half, wmma::row_major> af[WMI];
            wmma::fragment<wmma::matrix_b, 16, 16, 16, __half, wmma::col_major> bf[WNI];
            #pragma unroll
            for (int i = 0; i < WMI; i++)
                wmma::load_matrix_sync(af[i], As + (size_t)(wm0 + i * 16) * BKP + ks * 16, BKP);
            #pragma unroll
            for (int j = 0; j < WNI; j++)
                wmma::load_matrix_sync(bf[j], Bs + (size_t)(wn0 + j * 16) * BKP + ks * 16, BKP);
            #pragma unroll
            for (int i = 0; i < WMI; i++)
                #pragma unroll
                for (int j = 0; j < WNI; j++)
                    wmma::mma_sync(acc[i][j], af[i], bf[j], acc[i][j]);
        }
    }

    if (MODE == 0) {
        float* C = reinterpret_cast<float*>(Cout) + (size_t)blockIdx.z * csplit;
        #pragma unroll
        for (int i = 0; i < WMI; i++)
            #pragma unroll
            for (int j = 0; j < WNI; j++)
                wmma::store_matrix_sync(
                    &C[(size_t)(bm0 + wm0 + i * 16) * Ncols + (bn0 + wn0 + j * 16)],
                    acc[i][j], Ncols, wmma::mem_row_major);
    } else {
        // fused fp16 epilogue via SMEM scratch (stages no longer needed)
        __syncthreads();
        float* scr = reinterpret_cast<float*>(smem);      // [BM][EPI_LD]
        #pragma unroll
        for (int i = 0; i < WMI; i++)
            #pragma unroll
            for (int j = 0; j < WNI; j++)
                wmma::store_matrix_sync(
                    scr + (size_t)(wm0 + i * 16) * EPI_LD + (wn0 + j * 16),
                    acc[i][j], EPI_LD, wmma::mem_row_major);
        __syncthreads();
        __half* C = reinterpret_cast<__half*>(Cout);
        for (int idx = tid; idx < BM * (BN / 4); idx += NTHR) {
            const int row = idx >> 5;            // BN/4 = 32
            const int c4  = (idx & 31) * 4;
            float4 v = *reinterpret_cast<float4*>(scr + (size_t)row * EPI_LD + c4);
            float4 o;
            const float a = __ldg(rowvec + bm0 + row);
            if (MODE == 1) {
                o = make_float4(v.x * a, v.y * a, v.z * a, v.w * a);
            } else {
                float4 b = *reinterpret_cast<const float4*>(bias + bn0 + c4);
                o = make_float4(fmaxf(v.x + a * b.x, 0.f), fmaxf(v.y + a * b.y, 0.f),
                                fmaxf(v.z + a * b.z, 0.f), fmaxf(v.w + a * b.w, 0.f));
            }
            __half2* q = reinterpret_cast<__half2*>(C + (size_t)(bm0 + row) * Ncols + bn0 + c4);
            q[0] = __floats2half2_rn(o.x, o.y);
            q[1] = __floats2half2_rn(o.z, o.w);
        }
    }
}

// ---------------- pre/post kernels ----------------
// Pass 1 (fused): Ah[i,j] = fp16(edge[i,j]); inv[i] = rsqrt(rowsum fp32)
__global__ void convert_rowsum_inv(const float* __restrict__ edge,
                                   __half* __restrict__ Ah, float* __restrict__ inv) {
    const int row = blockIdx.x;
    const float4* p = reinterpret_cast<const float4*>(edge + (size_t)row * N_NODES);
    __half2* q = reinterpret_cast<__half2*>(Ah + (size_t)row * N_NODES);
    float s = 0.f;
    for (int j = threadIdx.x; j < N_NODES / 4; j += blockDim.x) {
        float4 v = p[j];
        q[j * 2]     = __floats2half2_rn(v.x, v.y);
        q[j * 2 + 1] = __floats2half2_rn(v.z, v.w);
        s += (v.x + v.y) + (v.z + v.w);
    }
    #pragma unroll
    for (int o = 16; o > 0; o >>= 1) s += __shfl_down_sync(0xffffffffu, s, o);
    __shared__ float red[8];
    const int lane = threadIdx.x & 31, w = threadIdx.x >> 5;
    if (lane == 0) red[w] = s;
    __syncthreads();
    if (w == 0) {
        s = (lane < 8) ? red[lane] : 0.f;
        #pragma unroll
        for (int o = 4; o > 0; o >>= 1) s += __shfl_down_sync(0xffffffffu, s, o);
        if (lane == 0) inv[row] = (s > 0.f) ? rsqrtf(s) : 0.f;
    }
}

// asum[i] = inv[i] * sum_j Ah[i,j]*inv[j]   (rowsum of effective Â)
__global__ void asum_gemv(const __half* __restrict__ Ah, const float* __restrict__ inv,
                          float* __restrict__ asum) {
    const int row = blockIdx.x;
    const __half2* p = reinterpret_cast<const __half2*>(Ah + (size_t)row * N_NODES);
    const float4* iv = reinterpret_cast<const float4*>(inv);
    float s = 0.f;
    for (int j = threadIdx.x; j < N_NODES / 4; j += blockDim.x) {
        __half2 h01 = p[j * 2], h23 = p[j * 2 + 1];
        float2 f01 = __half22float2(h01), f23 = __half22float2(h23);
        float4 w = iv[j];
        s += f01.x * w.x + f01.y * w.y + f23.x * w.z + f23.y * w.w;
    }
    #pragma unroll
    for (int o = 16; o > 0; o >>= 1) s += __shfl_down_sync(0xffffffffu, s, o);
    __shared__ float red[8];
    const int lane = threadIdx.x & 31, w = threadIdx.x >> 5;
    if (lane == 0) red[w] = s;
    __syncthreads();
    if (w == 0) {
        s = (lane < 8) ? red[lane] : 0.f;
        #pragma unroll
        for (int o = 4; o > 0; o >>= 1) s += __shfl_down_sync(0xffffffffu, s, o);
        if (lane == 0) asum[row] = s * __ldg(inv + row);
    }
}

// generic fp32 -> fp16 (4 per thread)
__global__ void conv_h(const float* __restrict__ in, __half* __restrict__ out) {
    const size_t i = ((size_t)blockIdx.x * blockDim.x + threadIdx.x) * 4;
    float4 v = *reinterpret_cast<const float4*>(in + i);
    __half2* q = reinterpret_cast<__half2*>(out + i);
    q[0] = __floats2half2_rn(v.x, v.y);
    q[1] = __floats2half2_rn(v.z, v.w);
}

// XTh[c, n] = fp16(inv[n] * X[n, c]); X is [N_NODES, IN_C]
__global__ void transpose_x_h(const float* __restrict__ X, const float* __restrict__ inv,
                              __half* __restrict__ XT) {
    __shared__ float t[32][33];
    const int bx = blockIdx.x * 32, by = blockIdx.y * 32;
    const int x = threadIdx.x, y = threadIdx.y;   // 32 x 8
    #pragma unroll
    for (int yy = y; yy < 32; yy += 8)
        t[yy][x] = X[(size_t)(by + yy) * IN_C + bx + x] * __ldg(inv + by + yy);
    __syncthreads();
    #pragma unroll
    for (int yy = y; yy < 32; yy += 8)
        XT[(size_t)(bx + yy) * N_NODES + by + x] = __float2half_rn(t[x][yy]);
}

// outT[n, m] = fp16(inv[m] * (D0[m,n] + D1[m,n])); D is [M, Ncols]
__global__ void epi_transpose_sum2_h(const float* __restrict__ D0, const float* __restrict__ D1,
                                     const float* __restrict__ inv,
                                     __half* __restrict__ outT, int M, int Ncols) {
    __shared__ float t[32][33];
    const int bx = blockIdx.x * 32, by = blockIdx.y * 32;
    const int x = threadIdx.x, y = threadIdx.y;   // 32 x 8
    #pragma unroll
    for (int yy = y; yy < 32; yy += 8) {
        const size_t idx = (size_t)(by + yy) * Ncols + bx + x;
        t[yy][x] = (D0[idx] + D1[idx]) * __ldg(inv + by + yy);
    }
    __syncthreads();
    #pragma unroll
    for (int yy = y; yy < 32; yy += 8)
        outT[(size_t)(bx + yy) * M + by + x] = __float2half_rn(t[x][yy]);
}

// out[m,j] = relu(inv[m]*(C0+C1) + asum[m]*b2[j])  (final, fp32)
__global__ void epi_relu_biasrow_sum2(const float* __restrict__ C0, const float* __restrict__ C1,
                                      const float* __restrict__ inv, const float* __restrict__ asum,
                                      const float* __restrict__ bias,
                                      float* __restrict__ out, int Ncols) {
    const size_t i = (size_t)blockIdx.x * blockDim.x + threadIdx.x;
    const int m  = (int)(i / (Ncols / 4));
    const int j4 = (int)(i % (Ncols / 4)) * 4;
    const float a = __ldg(asum + m);
    const float s = __ldg(inv + m);
    const size_t off = (size_t)m * Ncols + j4;
    float4 c0 = *reinterpret_cast<const float4*>(C0 + off);
    float4 c1 = *reinterpret_cast<const float4*>(C1 + off);
    float4 b  = *reinterpret_cast<const float4*>(bias + j4);
    float4 o = make_float4(fmaxf((c0.x + c1.x) * s + a * b.x, 0.f),
                           fmaxf((c0.y + c1.y) * s + a * b.y, 0.f),
                           fmaxf((c0.z + c1.z) * s + a * b.z, 0.f),
                           fmaxf((c0.w + c1.w) * s + a * b.w, 0.f));
    *reinterpret_cast<float4*>(out + off) = o;
}

// ---------------- launch ----------------
extern "C" void kernel_launch(void* const* d_in, const int* in_sizes, int n_in,
                              void* d_out, int out_size) {
    const float* point = (const float*)d_in[0];
    const float* edge  = (const float*)d_in[1];
    const float* W1    = (const float*)d_in[2];
    const float* b1    = (const float*)d_in[3];
    const float* W2    = (const float*)d_in[4];
    const float* b2    = (const float*)d_in[5];
    float* out = (float*)d_out;

    float *inv, *asum, *G, *C;
    __half *Ah, *XTh, *W1h, *W2h, *Gh, *Hh, *OsTh;
    cudaGetSymbolAddress((void**)&inv,  g_inv);
    cudaGetSymbolAddress((void**)&asum, g_asum);
    cudaGetSymbolAddress((void**)&Ah,   g_Ah);
    cudaGetSymbolAddress((void**)&XTh,  g_XTh);
    cudaGetSymbolAddress((void**)&W1h,  g_W1h);
    cudaGetSymbolAddress((void**)&W2h,  g_W2h);
    cudaGetSymbolAddress((void**)&Gh,   g_Gh);
    cudaGetSymbolAddress((void**)&Hh,   g_Hh);
    cudaGetSymbolAddress((void**)&OsTh, g_OsTh);
    cudaGetSymbolAddress((void**)&G,    g_G);
    cudaGetSymbolAddress((void**)&C,    g_C);

    cudaFuncSetAttribute(tc_gemm<0>, cudaFuncAttributeMaxDynamicSharedMemorySize, SMEM_GEMM);
    cudaFuncSetAttribute(tc_gemm<1>, cudaFuncAttributeMaxDynamicSharedMemorySize, SMEM_GEMM);
    cudaFuncSetAttribute(tc_gemm<2>, cudaFuncAttributeMaxDynamicSharedMemorySize, SMEM_GEMM);

    const size_t SPLIT = (size_t)N_NODES * OUT_C;   // split-K partial buffer stride

    // Side stream for aux work that is off the GEMM critical path.
    // Created per call, never destroyed (destroying a forked stream during an
    // active capture would invalidate the capture; leak is host-side only).
    cudaStream_t s2;
    cudaStreamCreateWithFlags(&s2, cudaStreamNonBlocking);
    cudaEvent_t ev0, evA, evJ;
    cudaEventCreateWithFlags(&ev0, cudaEventDisableTiming);
    cudaEventCreateWithFlags(&evA, cudaEventDisableTiming);
    cudaEventCreateWithFlags(&evJ, cudaEventDisableTiming);

    // Fork s2 from the (captured) main stream before launching anything on it.
    cudaEventRecord(ev0, 0);
    cudaStreamWaitEvent(s2, ev0, 0);

    // s2: weight conversions (no deps on edge pipeline)
    conv_h<<<(HID_C * IN_C / 4) / 256, 256, 0, s2>>>(W1, W1h);
    conv_h<<<(OUT_C * HID_C / 4) / 256, 256, 0, s2>>>(W2, W2h);

    // main: edge fp32 -> fp16 raw + rowsum + inv (single pass over edge)
    convert_rowsum_inv<<<N_NODES, 256>>>(edge, Ah, inv);
    cudaEventRecord(evA, 0);                 // Ah + inv ready
    cudaStreamWaitEvent(s2, evA, 0);
    // s2: asum = inv_i * (A_fp16 @ inv)  — overlaps with transpose_x + GEMM_a
    asum_gemv<<<N_NODES, 256, 0, s2>>>(Ah, inv, asum);
    cudaEventRecord(evJ, s2);                // join marker (asum, W1h, W2h done)

    // main: XTh = fp16(inv_n * X^T)
    transpose_x_h<<<dim3(IN_C / 32, N_NODES / 32), dim3(32, 8)>>>(point, inv, XTh);

    // main GEMM_a (MODE 1): Gh = fp16(inv_m * (A @ Xs))  [8192,512]  (256 CTAs)
    tc_gemm<1><<<dim3(IN_C / BN, N_NODES / BM, 1), NTHR, SMEM_GEMM>>>(
        Ah, XTh, Gh, N_NODES, N_NODES, N_NODES, IN_C, 0, inv, nullptr);

    // join: GEMM_b needs asum + W1h
    cudaStreamWaitEvent(0, evJ, 0);

    // GEMM_b (MODE 2): Hh = fp16(relu(G@W1^T + asum*b1))  [8192,1024]  (512 CTAs)
    tc_gemm<2><<<dim3(HID_C / BN, N_NODES / BM, 1), NTHR, SMEM_GEMM>>>(
        Gh, W1h, Hh, IN_C, IN_C, IN_C, HID_C, 0, asum, b1);

    // GEMM_c (MODE 0, split-K=2): D0,D1 = H@W2^T partials  [8192,256]  (256 CTAs)
    tc_gemm<0><<<dim3(OUT_C / BN, N_NODES / BM, 2), NTHR, SMEM_GEMM>>>(
        Hh, W2h, G, HID_C, HID_C, HID_C / 2, OUT_C, SPLIT, nullptr, nullptr);
    // OsTh = fp16(inv_m * (D0+D1)^T)
    epi_transpose_sum2_h<<<dim3(OUT_C / 32, N_NODES / 32), dim3(32, 8)>>>(
        G, G + SPLIT, inv, OsTh, N_NODES, OUT_C);

    // GEMM_d (MODE 0, split-K=2): C0,C1 = A@Os partials  [8192,256]  (256 CTAs)
    tc_gemm<0><<<dim3(OUT_C / BN, N_NODES / BM, 2), NTHR, SMEM_GEMM>>>(
        Ah, OsTh, C, N_NODES, N_NODES, N_NODES / 2, OUT_C, SPLIT, nullptr, nullptr);
    // out = relu(inv_m*(C0+C1) + asum*b2)
    epi_relu_biasrow_sum2<<<(N_NODES * OUT_C / 4) / 256, 256>>>(
        C, C + SPLIT, inv, asum, b2, out, OUT_C);
}